// round 1
// baseline (speedup 1.0000x reference)
#include <cuda_runtime.h>
#include <math.h>

#define T_TOK 2048
#define H_DIM 2048
#define E_NUM 64
#define TOPK 6
#define F_DIM 768
#define G_NUM 8
#define GSZ 8
#define KG_NUM 4
#define CAP 384
#define SCALEF 2.5f

#define BM 64
#define BN 64
#define BK 16

// ---------------- device scratch (static; no allocations) ----------------
__device__ int   g_cnt[E_NUM];
__device__ int   g_tok[E_NUM * CAP];
__device__ float g_wt [E_NUM * CAP];
__device__ float g_hbuf[(size_t)E_NUM * CAP * F_DIM];   // 75.5 MB
__device__ float g_tmp [(size_t)T_TOK * F_DIM];         // 6.3 MB

// ---------------- kernels ----------------
__global__ void zero_cnt_kernel() {
    if (threadIdx.x < E_NUM) g_cnt[threadIdx.x] = 0;
}

// One block per token. 64 threads: thread e computes logit for expert e.
__global__ void router_kernel(const float* __restrict__ x,
                              const float* __restrict__ gw,
                              const float* __restrict__ bias) {
    int t = blockIdx.x;
    int e = threadIdx.x;
    __shared__ float sc[E_NUM];
    __shared__ float scb[E_NUM];

    const float* xr = x + (size_t)t * H_DIM;
    float acc = 0.f;
    #pragma unroll 4
    for (int h = 0; h < H_DIM; h++) acc += xr[h] * gw[h * E_NUM + e];
    float s = 1.f / (1.f + __expf(-acc));
    sc[e]  = s;
    scb[e] = s + bias[e];
    __syncthreads();

    if (e == 0) {
        // group scores = sum of top-2 biased scores in each group of 8
        float gsc[G_NUM];
        for (int g = 0; g < G_NUM; g++) {
            float m1 = -1e30f, m2 = -1e30f;
            for (int i = 0; i < GSZ; i++) {
                float v = scb[g * GSZ + i];
                if (v > m1) { m2 = m1; m1 = v; }
                else if (v > m2) { m2 = v; }
            }
            gsc[g] = m1 + m2;
        }
        // pick top KG groups (ties -> lowest index, matching jax top_k)
        bool gsel[G_NUM];
        for (int g = 0; g < G_NUM; g++) gsel[g] = false;
        for (int r = 0; r < KG_NUM; r++) {
            int bi = -1; float bv = -1e30f;
            for (int g = 0; g < G_NUM; g++)
                if (!gsel[g] && gsc[g] > bv) { bv = gsc[g]; bi = g; }
            gsel[bi] = true;
        }
        // pick top K experts among allowed groups by biased score
        bool esel[E_NUM];
        for (int i = 0; i < E_NUM; i++) esel[i] = false;
        int ids[TOPK]; float ws[TOPK]; float wsum = 0.f;
        for (int r = 0; r < TOPK; r++) {
            int bi = -1; float bv = -1e30f;
            for (int ee = 0; ee < E_NUM; ee++) {
                if (!gsel[ee / GSZ] || esel[ee]) continue;
                float v = scb[ee];
                if (v > bv) { bv = v; bi = ee; }
            }
            esel[bi] = true; ids[r] = bi; ws[r] = sc[bi]; wsum += sc[bi];
        }
        float inv = SCALEF / wsum;
        for (int r = 0; r < TOPK; r++) {
            int ee = ids[r];
            int slot = atomicAdd(&g_cnt[ee], 1);
            if (slot < CAP) {
                g_tok[ee * CAP + slot] = t;
                g_wt [ee * CAP + slot] = ws[r] * inv;
            }
        }
    }
}

// Dual GEMM: C = silu(A@Wg) * (A@Wu).  A rows gathered by token index (EXPERT)
// or direct (shared expert).  Kdim = H_DIM, N = F_DIM.
template<bool EXPERT>
__global__ __launch_bounds__(256)
void gemm_gu_kernel(const float* __restrict__ x,
                    const float* __restrict__ Wg_all,
                    const float* __restrict__ Wu_all,
                    float* __restrict__ C_all) {
    int e = EXPERT ? blockIdx.z : 0;
    int M;
    const int* toks = nullptr;
    const float *Wg, *Wu;
    float* C;
    if (EXPERT) {
        M = min(g_cnt[e], CAP);
        toks = g_tok + e * CAP;
        Wg = Wg_all + (size_t)e * H_DIM * F_DIM;
        Wu = Wu_all + (size_t)e * H_DIM * F_DIM;
        C  = C_all  + (size_t)e * CAP * F_DIM;
    } else {
        M = T_TOK; Wg = Wg_all; Wu = Wu_all; C = C_all;
    }
    int m0 = blockIdx.y * BM;
    if (m0 >= M) return;
    int n0 = blockIdx.x * BN;

    __shared__ float As[BK][BM];
    __shared__ float Bg[BK][BN];
    __shared__ float Bu[BK][BN];

    int tid = threadIdx.x;
    int tx = tid & 15;
    int ty = tid >> 4;

    // A loader: row lm, 4 cols starting at lk
    int lm = tid >> 2;
    int lk = (tid & 3) * 4;
    int arow = m0 + lm;
    bool rowv = arow < M;
    const float* Arow;
    if (EXPERT) {
        int tk = rowv ? toks[arow] : 0;
        Arow = x + (size_t)tk * H_DIM;
    } else {
        Arow = x + (size_t)(rowv ? arow : 0) * H_DIM;
    }
    // B loader: row bk, 4 cols at bn
    int bk = tid >> 4;
    int bn = (tid & 15) * 4;

    float accg[4][4] = {}, accu[4][4] = {};

    for (int k0 = 0; k0 < H_DIM; k0 += BK) {
        float4 av = *(const float4*)(Arow + k0 + lk);
        As[lk + 0][lm] = av.x; As[lk + 1][lm] = av.y;
        As[lk + 2][lm] = av.z; As[lk + 3][lm] = av.w;
        *(float4*)&Bg[bk][bn] = *(const float4*)(Wg + (size_t)(k0 + bk) * F_DIM + n0 + bn);
        *(float4*)&Bu[bk][bn] = *(const float4*)(Wu + (size_t)(k0 + bk) * F_DIM + n0 + bn);
        __syncthreads();
        #pragma unroll
        for (int k = 0; k < BK; k++) {
            float4 a4 = *(const float4*)&As[k][ty * 4];
            float4 g4 = *(const float4*)&Bg[k][tx * 4];
            float4 u4 = *(const float4*)&Bu[k][tx * 4];
            float a[4] = {a4.x, a4.y, a4.z, a4.w};
            float g[4] = {g4.x, g4.y, g4.z, g4.w};
            float u[4] = {u4.x, u4.y, u4.z, u4.w};
            #pragma unroll
            for (int i = 0; i < 4; i++)
                #pragma unroll
                for (int j = 0; j < 4; j++) {
                    accg[i][j] += a[i] * g[j];
                    accu[i][j] += a[i] * u[j];
                }
        }
        __syncthreads();
    }

    #pragma unroll
    for (int i = 0; i < 4; i++) {
        int m = m0 + ty * 4 + i;
        if (m >= M) continue;
        float* crow = C + (size_t)m * F_DIM + n0;
        #pragma unroll
        for (int j = 0; j < 4; j++) {
            float g = accg[i][j], u = accu[i][j];
            crow[tx * 4 + j] = g / (1.f + __expf(-g)) * u;
        }
    }
}

// Down-proj: out = A @ W.  EXPERT: weighted atomicAdd scatter to token rows.
// Shared: plain store (first writer of d_out).  Kdim = F_DIM, N = H_DIM.
template<bool EXPERT>
__global__ __launch_bounds__(256)
void gemm_down_kernel(const float* __restrict__ A_all,
                      const float* __restrict__ W_all,
                      float* __restrict__ out) {
    int e = EXPERT ? blockIdx.z : 0;
    int M;
    const float *A, *W;
    const int* toks = nullptr;
    const float* wts = nullptr;
    if (EXPERT) {
        M = min(g_cnt[e], CAP);
        A = A_all + (size_t)e * CAP * F_DIM;
        W = W_all + (size_t)e * F_DIM * H_DIM;
        toks = g_tok + e * CAP;
        wts  = g_wt  + e * CAP;
    } else {
        M = T_TOK; A = A_all; W = W_all;
    }
    int m0 = blockIdx.y * BM;
    if (m0 >= M) return;
    int n0 = blockIdx.x * BN;

    __shared__ float As[BK][BM];
    __shared__ float Bs[BK][BN];

    int tid = threadIdx.x;
    int tx = tid & 15;
    int ty = tid >> 4;

    int lm = tid >> 2;
    int lk = (tid & 3) * 4;
    int arow = m0 + lm;
    bool rowv = arow < M;
    const float* Arow = A + (size_t)(rowv ? arow : 0) * F_DIM;

    int bk = tid >> 4;
    int bn = (tid & 15) * 4;

    float acc[4][4] = {};

    for (int k0 = 0; k0 < F_DIM; k0 += BK) {
        float4 av = *(const float4*)(Arow + k0 + lk);
        As[lk + 0][lm] = av.x; As[lk + 1][lm] = av.y;
        As[lk + 2][lm] = av.z; As[lk + 3][lm] = av.w;
        *(float4*)&Bs[bk][bn] = *(const float4*)(W + (size_t)(k0 + bk) * H_DIM + n0 + bn);
        __syncthreads();
        #pragma unroll
        for (int k = 0; k < BK; k++) {
            float4 a4 = *(const float4*)&As[k][ty * 4];
            float4 b4 = *(const float4*)&Bs[k][tx * 4];
            float a[4] = {a4.x, a4.y, a4.z, a4.w};
            float b[4] = {b4.x, b4.y, b4.z, b4.w};
            #pragma unroll
            for (int i = 0; i < 4; i++)
                #pragma unroll
                for (int j = 0; j < 4; j++)
                    acc[i][j] += a[i] * b[j];
        }
        __syncthreads();
    }

    #pragma unroll
    for (int i = 0; i < 4; i++) {
        int m = m0 + ty * 4 + i;
        if (m >= M) continue;
        if (EXPERT) {
            float w = wts[m];
            float* orow = out + (size_t)toks[m] * H_DIM + n0;
            #pragma unroll
            for (int j = 0; j < 4; j++)
                atomicAdd(&orow[tx * 4 + j], acc[i][j] * w);
        } else {
            float* orow = out + (size_t)m * H_DIM + n0;
            #pragma unroll
            for (int j = 0; j < 4; j++)
                orow[tx * 4 + j] = acc[i][j];
        }
    }
}

// ---------------- launch ----------------
extern "C" void kernel_launch(void* const* d_in, const int* in_sizes, int n_in,
                              void* d_out, int out_size) {
    const float* x       = (const float*)d_in[0];  // [2,1024,2048]
    const float* gate_w  = (const float*)d_in[1];  // [2048,64]
    const float* bias    = (const float*)d_in[2];  // [64]
    const float* w_gate  = (const float*)d_in[3];  // [64,2048,768]
    const float* w_up    = (const float*)d_in[4];  // [64,2048,768]
    const float* w_down  = (const float*)d_in[5];  // [64,768,2048]
    const float* ws_gate = (const float*)d_in[6];  // [2048,768]
    const float* ws_up   = (const float*)d_in[7];  // [2048,768]
    const float* ws_down = (const float*)d_in[8];  // [768,2048]
    float* out = (float*)d_out;

    float* tmp;  cudaGetSymbolAddress((void**)&tmp,  g_tmp);
    float* hbuf; cudaGetSymbolAddress((void**)&hbuf, g_hbuf);

    zero_cnt_kernel<<<1, 64>>>();
    router_kernel<<<T_TOK, 64>>>(x, gate_w, bias);

    // shared expert first: plain stores initialize d_out
    gemm_gu_kernel<false><<<dim3(F_DIM / BN, T_TOK / BM, 1), 256>>>(x, ws_gate, ws_up, tmp);
    gemm_down_kernel<false><<<dim3(H_DIM / BN, T_TOK / BM, 1), 256>>>(tmp, ws_down, out);

    // routed experts: atomicAdd on top
    gemm_gu_kernel<true><<<dim3(F_DIM / BN, CAP / BM, E_NUM), 256>>>(x, w_gate, w_up, hbuf);
    gemm_down_kernel<true><<<dim3(H_DIM / BN, CAP / BM, E_NUM), 256>>>(hbuf, w_down, out);
}

// round 3
// speedup vs baseline: 1.7621x; 1.7621x over previous
#include <cuda_runtime.h>
#include <cuda_bf16.h>
#include <math.h>

#define T_TOK 2048
#define H_DIM 2048
#define E_NUM 64
#define TOPK 6
#define F_DIM 768
#define G_NUM 8
#define GSZ 8
#define KG_NUM 4
#define CAP 384
#define SCALEF 2.5f

// GEMM tile config
#define BM 256
#define BN 64
#define BK 32
#define NTHREADS 512

// smem layout (element offsets, bf16)
#define SA 40                     // A row stride (BK + 8)
#define SB 72                     // B row stride (BN + 8)
#define OFF_ALO   (BM * SA)           // 10240
#define OFF_B0HI  (2 * BM * SA)       // 20480
#define OFF_B0LO  (OFF_B0HI + BK * SB)
#define OFF_B1HI  (OFF_B0LO + BK * SB)
#define OFF_B1LO  (OFF_B1HI + BK * SB)
#define SMEM_DUAL_BYTES   ((OFF_B1LO + BK * SB) * 2)
#define SMEM_SINGLE_BYTES ((OFF_B0LO + BK * SB) * 2)

// ---------------- device scratch ----------------
__device__ int   g_cnt[E_NUM];
__device__ int   g_tok[E_NUM * CAP];
__device__ float g_wt [E_NUM * CAP];
__device__ float g_hbuf[(size_t)E_NUM * CAP * F_DIM];   // 75.5 MB
__device__ float g_tmp [(size_t)T_TOK * F_DIM];         // 6.3 MB

// ---------------- helpers ----------------
__device__ __forceinline__ void ldsm4(unsigned r[4], unsigned addr) {
    asm volatile("ldmatrix.sync.aligned.m8n8.x4.shared.b16 {%0,%1,%2,%3}, [%4];\n"
        : "=r"(r[0]), "=r"(r[1]), "=r"(r[2]), "=r"(r[3]) : "r"(addr));
}
__device__ __forceinline__ void ldsm4t(unsigned r[4], unsigned addr) {
    asm volatile("ldmatrix.sync.aligned.m8n8.x4.trans.shared.b16 {%0,%1,%2,%3}, [%4];\n"
        : "=r"(r[0]), "=r"(r[1]), "=r"(r[2]), "=r"(r[3]) : "r"(addr));
}
__device__ __forceinline__ void mma_bf16(float c[4], const unsigned a[4],
                                         unsigned b0, unsigned b1) {
    asm volatile(
        "mma.sync.aligned.m16n8k16.row.col.f32.bf16.bf16.f32 "
        "{%0,%1,%2,%3},{%4,%5,%6,%7},{%8,%9},{%0,%1,%2,%3};\n"
        : "+f"(c[0]), "+f"(c[1]), "+f"(c[2]), "+f"(c[3])
        : "r"(a[0]), "r"(a[1]), "r"(a[2]), "r"(a[3]), "r"(b0), "r"(b1));
}

__device__ __forceinline__ void split_store(__nv_bfloat16* hi, __nv_bfloat16* lo,
                                            int off, float4 v) {
    __nv_bfloat16 h0 = __float2bfloat16_rn(v.x);
    __nv_bfloat16 h1 = __float2bfloat16_rn(v.y);
    __nv_bfloat16 h2 = __float2bfloat16_rn(v.z);
    __nv_bfloat16 h3 = __float2bfloat16_rn(v.w);
    __nv_bfloat16 l0 = __float2bfloat16_rn(v.x - __bfloat162float(h0));
    __nv_bfloat16 l1 = __float2bfloat16_rn(v.y - __bfloat162float(h1));
    __nv_bfloat16 l2 = __float2bfloat16_rn(v.z - __bfloat162float(h2));
    __nv_bfloat16 l3 = __float2bfloat16_rn(v.w - __bfloat162float(h3));
    union { __nv_bfloat16 b[4]; uint2 u; } H, L;
    H.b[0] = h0; H.b[1] = h1; H.b[2] = h2; H.b[3] = h3;
    L.b[0] = l0; L.b[1] = l1; L.b[2] = l2; L.b[3] = l3;
    *(uint2*)(hi + off) = H.u;
    *(uint2*)(lo + off) = L.u;
}

// ---------------- small kernels ----------------
__global__ void zero_cnt_kernel() {
    if (threadIdx.x < E_NUM) g_cnt[threadIdx.x] = 0;
}

__global__ void router_kernel(const float* __restrict__ x,
                              const float* __restrict__ gw,
                              const float* __restrict__ bias) {
    int t = blockIdx.x;
    int tid = threadIdx.x;
    int e = tid & 63, part = tid >> 6;   // 4 partial sums per expert
    __shared__ float ps[4][E_NUM];
    __shared__ float sc[E_NUM];
    __shared__ float scb[E_NUM];

    const float* xr = x + (size_t)t * H_DIM;
    float acc = 0.f;
    int h0 = part * (H_DIM / 4);
    #pragma unroll 4
    for (int h = 0; h < H_DIM / 4; h++)
        acc += xr[h0 + h] * gw[(size_t)(h0 + h) * E_NUM + e];
    ps[part][e] = acc;
    __syncthreads();

    if (tid < E_NUM) {
        float l = ps[0][e] + ps[1][e] + ps[2][e] + ps[3][e];
        float s = 1.f / (1.f + __expf(-l));
        sc[e] = s;
        scb[e] = s + bias[e];
    }
    __syncthreads();

    if (tid == 0) {
        float gsc[G_NUM];
        for (int g = 0; g < G_NUM; g++) {
            float m1 = -1e30f, m2 = -1e30f;
            for (int i = 0; i < GSZ; i++) {
                float v = scb[g * GSZ + i];
                if (v > m1) { m2 = m1; m1 = v; }
                else if (v > m2) { m2 = v; }
            }
            gsc[g] = m1 + m2;
        }
        bool gsel[G_NUM];
        for (int g = 0; g < G_NUM; g++) gsel[g] = false;
        for (int r = 0; r < KG_NUM; r++) {
            int bi = -1; float bv = -1e30f;
            for (int g = 0; g < G_NUM; g++)
                if (!gsel[g] && gsc[g] > bv) { bv = gsc[g]; bi = g; }
            gsel[bi] = true;
        }
        bool esel[E_NUM];
        for (int i = 0; i < E_NUM; i++) esel[i] = false;
        int ids[TOPK]; float ws[TOPK]; float wsum = 0.f;
        for (int r = 0; r < TOPK; r++) {
            int bi = -1; float bv = -1e30f;
            for (int ee = 0; ee < E_NUM; ee++) {
                if (!gsel[ee / GSZ] || esel[ee]) continue;
                float v = scb[ee];
                if (v > bv) { bv = v; bi = ee; }
            }
            esel[bi] = true; ids[r] = bi; ws[r] = sc[bi]; wsum += sc[bi];
        }
        float inv = SCALEF / wsum;
        for (int r = 0; r < TOPK; r++) {
            int ee = ids[r];
            int slot = atomicAdd(&g_cnt[ee], 1);
            if (slot < CAP) {
                g_tok[ee * CAP + slot] = t;
                g_wt [ee * CAP + slot] = ws[r] * inv;
            }
        }
    }
}

// ---------------- tensor-core GEMM ----------------
// C = A @ W0 (and silu(A@W0)*(A@W1) when DUAL). fp32 in/out, bf16 hi/lo x3 MMA.
// EXPERT&&DUAL : A rows gathered from x via g_tok (gate/up expert GEMM)
// EXPERT&&!DUAL: A = g_hbuf slice, epilogue = weighted atomicAdd scatter to out
template<bool EXPERT, bool DUAL, int KDIM, int NDIM>
__global__ __launch_bounds__(NTHREADS, 1)
void mma_gemm(const float* __restrict__ Abase,
              const float* __restrict__ W0base,
              const float* __restrict__ W1base,
              float* __restrict__ Cbase) {
    constexpr bool GATHER  = EXPERT && DUAL;
    constexpr bool SCATTER = EXPERT && !DUAL;

    const int e = EXPERT ? blockIdx.z : 0;
    const int M = EXPERT ? min(g_cnt[e], CAP) : T_TOK;
    const int m0 = blockIdx.y * BM;
    if (m0 >= M) return;
    const int n0 = blockIdx.x * BN;

    const int* toks = EXPERT ? (g_tok + e * CAP) : nullptr;
    const float* A  = GATHER ? Abase
                             : (EXPERT ? Abase + (size_t)e * CAP * KDIM : Abase);
    const float* W0 = EXPERT ? W0base + (size_t)e * KDIM * NDIM : W0base;
    const float* W1 = nullptr;
    if (DUAL) W1 = EXPERT ? W1base + (size_t)e * KDIM * NDIM : W1base;
    float* C = DUAL ? (EXPERT ? Cbase + (size_t)e * CAP * NDIM : Cbase) : Cbase;

    extern __shared__ char smem_raw[];
    __nv_bfloat16* sm = (__nv_bfloat16*)smem_raw;
    __nv_bfloat16* Ahi  = sm;
    __nv_bfloat16* Alo  = sm + OFF_ALO;
    __nv_bfloat16* B0hi = sm + OFF_B0HI;
    __nv_bfloat16* B0lo = sm + OFF_B0LO;
    __nv_bfloat16* B1hi = sm + OFF_B1HI;
    __nv_bfloat16* B1lo = sm + OFF_B1LO;

    const int tid  = threadIdx.x;
    const int lane = tid & 31;
    const int wid  = tid >> 5;
    const int wm = wid & 7;     // 8 warp rows (32 m each)
    const int wn = wid >> 3;    // 2 warp cols (32 n each)

    // ----- staging assignments -----
    const float* aptr[4];
    int aoffs[4];
    #pragma unroll
    for (int i = 0; i < 4; i++) {
        int idx = tid + i * NTHREADS;
        int row = idx >> 3;              // 0..255
        int c4  = (idx & 7) * 4;         // 0..28
        aoffs[i] = row * SA + c4;
        int gr = m0 + row;
        if (GATHER) {
            int tk = (gr < M) ? toks[gr] : toks[0];
            aptr[i] = A + (size_t)tk * KDIM + c4;
        } else {
            int r = (gr < M) ? gr : (M - 1);
            aptr[i] = A + (size_t)r * KDIM + c4;
        }
    }
    const int brow = tid >> 4;           // 0..31
    const int bc4  = (tid & 15) * 4;     // 0..60
    const int boffs = brow * SB + bc4;
    const float* bptr0 = W0 + (size_t)brow * NDIM + n0 + bc4;
    const float* bptr1 = DUAL ? (W1 + (size_t)brow * NDIM + n0 + bc4) : nullptr;

    // ----- ldmatrix addresses -----
    unsigned sbase = (unsigned)__cvta_generic_to_shared(smem_raw);
    const int ar  = lane & 15;
    const int ac8 = (lane >> 4) * 8;
    unsigned a_addr = sbase + ((wm * 32 + ar) * SA + ac8) * 2;
    unsigned b_addr = sbase + OFF_B0HI * 2 + ((lane & 15) * SB + wn * 32 + ac8) * 2;

    float accg[2][4][4] = {};
    float accu[2][4][4] = {};

    for (int k0 = 0; k0 < KDIM; k0 += BK) {
        // stage A (fp32 -> bf16 hi/lo)
        #pragma unroll
        for (int i = 0; i < 4; i++) {
            float4 v = *(const float4*)(aptr[i] + k0);
            split_store(Ahi, Alo, aoffs[i], v);
        }
        // stage B
        {
            float4 v = *(const float4*)(bptr0 + (size_t)k0 * NDIM);
            split_store(B0hi, B0lo, boffs, v);
            if (DUAL) {
                float4 w = *(const float4*)(bptr1 + (size_t)k0 * NDIM);
                split_store(B1hi, B1lo, boffs, w);
            }
        }
        __syncthreads();

        #pragma unroll
        for (int kk = 0; kk < BK; kk += 16) {
            unsigned ah[2][4], al[2][4];
            #pragma unroll
            for (int mi = 0; mi < 2; mi++) {
                unsigned ad = a_addr + (mi * 16 * SA + kk) * 2;
                ldsm4(ah[mi], ad);
                ldsm4(al[mi], ad + OFF_ALO * 2);
            }
            // W0 (gate / down)
            #pragma unroll
            for (int nj = 0; nj < 2; nj++) {
                unsigned bh[4], bl[4];
                unsigned bd = b_addr + (kk * SB + nj * 16) * 2;
                ldsm4t(bh, bd);
                ldsm4t(bl, bd + BK * SB * 2);
                #pragma unroll
                for (int mi = 0; mi < 2; mi++)
                    #pragma unroll
                    for (int s = 0; s < 2; s++) {
                        float* c = accg[mi][nj * 2 + s];
                        mma_bf16(c, ah[mi], bh[2 * s], bh[2 * s + 1]);
                        mma_bf16(c, ah[mi], bl[2 * s], bl[2 * s + 1]);
                        mma_bf16(c, al[mi], bh[2 * s], bh[2 * s + 1]);
                    }
            }
            if (DUAL) {
                #pragma unroll
                for (int nj = 0; nj < 2; nj++) {
                    unsigned bh[4], bl[4];
                    unsigned bd = b_addr + (2 * BK * SB + kk * SB + nj * 16) * 2;
                    ldsm4t(bh, bd);
                    ldsm4t(bl, bd + BK * SB * 2);
                    #pragma unroll
                    for (int mi = 0; mi < 2; mi++)
                        #pragma unroll
                        for (int s = 0; s < 2; s++) {
                            float* c = accu[mi][nj * 2 + s];
                            mma_bf16(c, ah[mi], bh[2 * s], bh[2 * s + 1]);
                            mma_bf16(c, ah[mi], bl[2 * s], bl[2 * s + 1]);
                            mma_bf16(c, al[mi], bh[2 * s], bh[2 * s + 1]);
                        }
                }
            }
        }
        __syncthreads();
    }

    // ----- epilogue -----
    const int g  = lane >> 2;
    const int t4 = lane & 3;
    #pragma unroll
    for (int mi = 0; mi < 2; mi++) {
        #pragma unroll
        for (int nc = 0; nc < 4; nc++) {
            int col = n0 + wn * 32 + nc * 8 + t4 * 2;
            #pragma unroll
            for (int h = 0; h < 2; h++) {
                int m = m0 + wm * 32 + mi * 16 + g + h * 8;
                if (m >= M) continue;
                float c0 = accg[mi][nc][h * 2];
                float c1 = accg[mi][nc][h * 2 + 1];
                if (DUAL) {
                    float u0 = accu[mi][nc][h * 2];
                    float u1 = accu[mi][nc][h * 2 + 1];
                    float v0 = c0 / (1.f + __expf(-c0)) * u0;
                    float v1 = c1 / (1.f + __expf(-c1)) * u1;
                    float2 o = make_float2(v0, v1);
                    *(float2*)(C + (size_t)m * NDIM + col) = o;
                } else if (SCATTER) {
                    float w = g_wt[e * CAP + m];
                    float* o = C + (size_t)toks[m] * NDIM + col;
                    atomicAdd(o, c0 * w);
                    atomicAdd(o + 1, c1 * w);
                } else {
                    float2 o = make_float2(c0, c1);
                    *(float2*)(C + (size_t)m * NDIM + col) = o;
                }
            }
        }
    }
}

// ---------------- launch ----------------
extern "C" void kernel_launch(void* const* d_in, const int* in_sizes, int n_in,
                              void* d_out, int out_size) {
    const float* x       = (const float*)d_in[0];
    const float* gate_w  = (const float*)d_in[1];
    const float* bias    = (const float*)d_in[2];
    const float* w_gate  = (const float*)d_in[3];
    const float* w_up    = (const float*)d_in[4];
    const float* w_down  = (const float*)d_in[5];
    const float* ws_gate = (const float*)d_in[6];
    const float* ws_up   = (const float*)d_in[7];
    const float* ws_down = (const float*)d_in[8];
    float* out = (float*)d_out;

    float* tmp;  cudaGetSymbolAddress((void**)&tmp,  g_tmp);
    float* hbuf; cudaGetSymbolAddress((void**)&hbuf, g_hbuf);

    cudaFuncSetAttribute(mma_gemm<false, true,  H_DIM, F_DIM>,
                         cudaFuncAttributeMaxDynamicSharedMemorySize, SMEM_DUAL_BYTES);
    cudaFuncSetAttribute(mma_gemm<false, false, F_DIM, H_DIM>,
                         cudaFuncAttributeMaxDynamicSharedMemorySize, SMEM_SINGLE_BYTES);
    cudaFuncSetAttribute(mma_gemm<true,  true,  H_DIM, F_DIM>,
                         cudaFuncAttributeMaxDynamicSharedMemorySize, SMEM_DUAL_BYTES);
    cudaFuncSetAttribute(mma_gemm<true,  false, F_DIM, H_DIM>,
                         cudaFuncAttributeMaxDynamicSharedMemorySize, SMEM_SINGLE_BYTES);

    zero_cnt_kernel<<<1, 64>>>();
    router_kernel<<<T_TOK, 256>>>(x, gate_w, bias);

    // shared expert (plain stores initialize d_out)
    mma_gemm<false, true, H_DIM, F_DIM>
        <<<dim3(F_DIM / BN, T_TOK / BM, 1), NTHREADS, SMEM_DUAL_BYTES>>>(
            x, ws_gate, ws_up, tmp);
    mma_gemm<false, false, F_DIM, H_DIM>
        <<<dim3(H_DIM / BN, T_TOK / BM, 1), NTHREADS, SMEM_SINGLE_BYTES>>>(
            tmp, ws_down, nullptr, out);

    // routed experts
    mma_gemm<true, true, H_DIM, F_DIM>
        <<<dim3(F_DIM / BN, (CAP + BM - 1) / BM, E_NUM), NTHREADS, SMEM_DUAL_BYTES>>>(
            x, w_gate, w_up, hbuf);
    mma_gemm<true, false, F_DIM, H_DIM>
        <<<dim3(H_DIM / BN, (CAP + BM - 1) / BM, E_NUM), NTHREADS, SMEM_SINGLE_BYTES>>>(
            hbuf, w_down, nullptr, out);
}

// round 4
// speedup vs baseline: 1.8976x; 1.0769x over previous
#include <cuda_runtime.h>
#include <cuda_bf16.h>
#include <math.h>

#define T_TOK 2048
#define H_DIM 2048
#define E_NUM 64
#define TOPK 6
#define F_DIM 768
#define G_NUM 8
#define GSZ 8
#define KG_NUM 4
#define CAP 384
#define SCALEF 2.5f

// GEMM tile config
#define BM 256
#define BN 64
#define BK 32
#define NTHREADS 512

// smem layout (element offsets, bf16) within ONE buffer
#define SA 40                     // A row stride
#define SB 72                     // B row stride
#define OFF_ALO   (BM * SA)               // 10240
#define OFF_B     (2 * BM * SA)           // 20480  (B matrices start)
#define BTILE     (BK * SB)               // 2304
#define BUFE_DUAL   (OFF_B + 4 * BTILE)   // 29696 elems
#define BUFE_SINGLE (OFF_B + 2 * BTILE)   // 25088 elems
#define SMEM_DUAL_BYTES   (2 * BUFE_DUAL * 2)
#define SMEM_SINGLE_BYTES (2 * BUFE_SINGLE * 2)

// ---------------- device scratch ----------------
__device__ int   g_cnt[E_NUM];
__device__ int   g_tok[E_NUM * CAP];
__device__ float g_wt [E_NUM * CAP];
__device__ float g_hbuf[(size_t)E_NUM * CAP * F_DIM];
__device__ float g_tmp [(size_t)T_TOK * F_DIM];

// ---------------- helpers ----------------
__device__ __forceinline__ void ldsm4(unsigned r[4], unsigned addr) {
    asm volatile("ldmatrix.sync.aligned.m8n8.x4.shared.b16 {%0,%1,%2,%3}, [%4];\n"
        : "=r"(r[0]), "=r"(r[1]), "=r"(r[2]), "=r"(r[3]) : "r"(addr));
}
__device__ __forceinline__ void ldsm4t(unsigned r[4], unsigned addr) {
    asm volatile("ldmatrix.sync.aligned.m8n8.x4.trans.shared.b16 {%0,%1,%2,%3}, [%4];\n"
        : "=r"(r[0]), "=r"(r[1]), "=r"(r[2]), "=r"(r[3]) : "r"(addr));
}
__device__ __forceinline__ void mma_bf16(float c[4], const unsigned a[4],
                                         unsigned b0, unsigned b1) {
    asm volatile(
        "mma.sync.aligned.m16n8k16.row.col.f32.bf16.bf16.f32 "
        "{%0,%1,%2,%3},{%4,%5,%6,%7},{%8,%9},{%0,%1,%2,%3};\n"
        : "+f"(c[0]), "+f"(c[1]), "+f"(c[2]), "+f"(c[3])
        : "r"(a[0]), "r"(a[1]), "r"(a[2]), "r"(a[3]), "r"(b0), "r"(b1));
}

__device__ __forceinline__ void split_store(__nv_bfloat16* hi, __nv_bfloat16* lo,
                                            int off, float4 v) {
    __nv_bfloat16 h0 = __float2bfloat16_rn(v.x);
    __nv_bfloat16 h1 = __float2bfloat16_rn(v.y);
    __nv_bfloat16 h2 = __float2bfloat16_rn(v.z);
    __nv_bfloat16 h3 = __float2bfloat16_rn(v.w);
    __nv_bfloat16 l0 = __float2bfloat16_rn(v.x - __bfloat162float(h0));
    __nv_bfloat16 l1 = __float2bfloat16_rn(v.y - __bfloat162float(h1));
    __nv_bfloat16 l2 = __float2bfloat16_rn(v.z - __bfloat162float(h2));
    __nv_bfloat16 l3 = __float2bfloat16_rn(v.w - __bfloat162float(h3));
    union { __nv_bfloat16 b[4]; uint2 u; } H, L;
    H.b[0] = h0; H.b[1] = h1; H.b[2] = h2; H.b[3] = h3;
    L.b[0] = l0; L.b[1] = l1; L.b[2] = l2; L.b[3] = l3;
    *(uint2*)(hi + off) = H.u;
    *(uint2*)(lo + off) = L.u;
}

// ---------------- small kernels ----------------
__global__ void zero_cnt_kernel() {
    if (threadIdx.x < E_NUM) g_cnt[threadIdx.x] = 0;
}

__global__ void router_kernel(const float* __restrict__ x,
                              const float* __restrict__ gw,
                              const float* __restrict__ bias) {
    int t = blockIdx.x;
    int tid = threadIdx.x;
    int e = tid & 63, part = tid >> 6;
    __shared__ float ps[4][E_NUM];
    __shared__ float sc[E_NUM];
    __shared__ float scb[E_NUM];

    const float* xr = x + (size_t)t * H_DIM;
    float acc = 0.f;
    int h0 = part * (H_DIM / 4);
    #pragma unroll 4
    for (int h = 0; h < H_DIM / 4; h++)
        acc += xr[h0 + h] * gw[(size_t)(h0 + h) * E_NUM + e];
    ps[part][e] = acc;
    __syncthreads();

    if (tid < E_NUM) {
        float l = ps[0][e] + ps[1][e] + ps[2][e] + ps[3][e];
        float s = 1.f / (1.f + __expf(-l));
        sc[e] = s;
        scb[e] = s + bias[e];
    }
    __syncthreads();

    if (tid == 0) {
        float gsc[G_NUM];
        for (int g = 0; g < G_NUM; g++) {
            float m1 = -1e30f, m2 = -1e30f;
            for (int i = 0; i < GSZ; i++) {
                float v = scb[g * GSZ + i];
                if (v > m1) { m2 = m1; m1 = v; }
                else if (v > m2) { m2 = v; }
            }
            gsc[g] = m1 + m2;
        }
        bool gsel[G_NUM];
        for (int g = 0; g < G_NUM; g++) gsel[g] = false;
        for (int r = 0; r < KG_NUM; r++) {
            int bi = -1; float bv = -1e30f;
            for (int g = 0; g < G_NUM; g++)
                if (!gsel[g] && gsc[g] > bv) { bv = gsc[g]; bi = g; }
            gsel[bi] = true;
        }
        bool esel[E_NUM];
        for (int i = 0; i < E_NUM; i++) esel[i] = false;
        int ids[TOPK]; float ws[TOPK]; float wsum = 0.f;
        for (int r = 0; r < TOPK; r++) {
            int bi = -1; float bv = -1e30f;
            for (int ee = 0; ee < E_NUM; ee++) {
                if (!gsel[ee / GSZ] || esel[ee]) continue;
                float v = scb[ee];
                if (v > bv) { bv = v; bi = ee; }
            }
            esel[bi] = true; ids[r] = bi; ws[r] = sc[bi]; wsum += sc[bi];
        }
        float inv = SCALEF / wsum;
        for (int r = 0; r < TOPK; r++) {
            int ee = ids[r];
            int slot = atomicAdd(&g_cnt[ee], 1);
            if (slot < CAP) {
                g_tok[ee * CAP + slot] = t;
                g_wt [ee * CAP + slot] = ws[r] * inv;
            }
        }
    }
}

// ---------------- tensor-core GEMM (double-buffered) ----------------
template<bool EXPERT, bool DUAL, int KDIM, int NDIM>
__global__ __launch_bounds__(NTHREADS, 1)
void mma_gemm(const float* __restrict__ Abase,
              const float* __restrict__ W0base,
              const float* __restrict__ W1base,
              float* __restrict__ Cbase) {
    constexpr bool GATHER  = EXPERT && DUAL;
    constexpr bool SCATTER = EXPERT && !DUAL;
    constexpr int  BUFE    = DUAL ? BUFE_DUAL : BUFE_SINGLE;

    const int e = EXPERT ? blockIdx.z : 0;
    const int M = EXPERT ? min(g_cnt[e], CAP) : T_TOK;
    const int m0 = blockIdx.y * BM;
    if (m0 >= M) return;
    const int n0 = blockIdx.x * BN;

    const int* toks = EXPERT ? (g_tok + e * CAP) : nullptr;
    const float* A  = GATHER ? Abase
                             : (EXPERT ? Abase + (size_t)e * CAP * KDIM : Abase);
    const float* W0 = EXPERT ? W0base + (size_t)e * KDIM * NDIM : W0base;
    const float* W1 = nullptr;
    if (DUAL) W1 = EXPERT ? W1base + (size_t)e * KDIM * NDIM : W1base;
    float* C = DUAL ? (EXPERT ? Cbase + (size_t)e * CAP * NDIM : Cbase) : Cbase;

    extern __shared__ char smem_raw[];
    __nv_bfloat16* sm = (__nv_bfloat16*)smem_raw;

    const int tid  = threadIdx.x;
    const int lane = tid & 31;
    const int wid  = tid >> 5;
    const int wm = wid & 7;     // 8 warp rows (32 m each)
    const int wn = wid >> 3;    // 2 warp cols (32 n each)

    // ----- staging assignments -----
    const float* aptr[4];
    int aoffs[4];
    #pragma unroll
    for (int i = 0; i < 4; i++) {
        int idx = tid + i * NTHREADS;
        int row = idx >> 3;              // 0..255
        int c4  = (idx & 7) * 4;
        aoffs[i] = row * SA + c4;
        int gr = m0 + row;
        if (GATHER) {
            int tk = (gr < M) ? toks[gr] : toks[0];
            aptr[i] = A + (size_t)tk * KDIM + c4;
        } else {
            int r = (gr < M) ? gr : (M - 1);
            aptr[i] = A + (size_t)r * KDIM + c4;
        }
    }
    const int brow = tid >> 4;           // 0..31
    const int bc4  = (tid & 15) * 4;
    const int boffs = brow * SB + bc4;
    const float* bptr0 = W0 + (size_t)brow * NDIM + n0 + bc4;
    const float* bptr1 = DUAL ? (W1 + (size_t)brow * NDIM + n0 + bc4) : nullptr;

    // ----- ldmatrix addresses (relative to buffer start) -----
    unsigned sbase = (unsigned)__cvta_generic_to_shared(smem_raw);
    const int ar  = lane & 15;
    const int ac8 = (lane >> 4) * 8;
    unsigned a_rel = ((wm * 32 + ar) * SA + ac8) * 2;
    unsigned b_rel = (OFF_B + (lane & 15) * SB + wn * 32 + ac8) * 2;

    float accg[2][4][4] = {};
    float accu[2][4][4] = {};

    // prefetch registers
    float4 avr[4];
    float4 bvr0, bvr1;

    // prologue: load tile 0
    #pragma unroll
    for (int i = 0; i < 4; i++) avr[i] = *(const float4*)(aptr[i]);
    bvr0 = *(const float4*)(bptr0);
    if (DUAL) bvr1 = *(const float4*)(bptr1);

    constexpr int NIT = KDIM / BK;
    #pragma unroll 1
    for (int it = 0; it < NIT; it++) {
        const int bufo = (it & 1) ? BUFE : 0;
        __nv_bfloat16* Ahi  = sm + bufo;
        __nv_bfloat16* Alo  = Ahi + OFF_ALO;
        __nv_bfloat16* B0hi = sm + bufo + OFF_B;
        __nv_bfloat16* B0lo = B0hi + BTILE;

        // STS current prefetch
        #pragma unroll
        for (int i = 0; i < 4; i++) split_store(Ahi, Alo, aoffs[i], avr[i]);
        split_store(B0hi, B0lo, boffs, bvr0);
        if (DUAL) split_store(B0hi + 2 * BTILE, B0lo + 2 * BTILE, boffs, bvr1);

        // LDG next tile
        if (it + 1 < NIT) {
            const int k = (it + 1) * BK;
            #pragma unroll
            for (int i = 0; i < 4; i++) avr[i] = *(const float4*)(aptr[i] + k);
            bvr0 = *(const float4*)(bptr0 + (size_t)k * NDIM);
            if (DUAL) bvr1 = *(const float4*)(bptr1 + (size_t)k * NDIM);
        }
        __syncthreads();

        // compute on this buffer
        const unsigned a_addr = sbase + bufo * 2 + a_rel;
        const unsigned b_addr = sbase + bufo * 2 + b_rel;
        #pragma unroll
        for (int kk = 0; kk < BK; kk += 16) {
            unsigned ah[2][4], al[2][4];
            #pragma unroll
            for (int mi = 0; mi < 2; mi++) {
                unsigned ad = a_addr + (mi * 16 * SA + kk) * 2;
                ldsm4(ah[mi], ad);
                ldsm4(al[mi], ad + OFF_ALO * 2);
            }
            #pragma unroll
            for (int nj = 0; nj < 2; nj++) {
                unsigned bh[4], bl[4];
                unsigned bd = b_addr + (kk * SB + nj * 16) * 2;
                ldsm4t(bh, bd);
                ldsm4t(bl, bd + BTILE * 2);
                #pragma unroll
                for (int mi = 0; mi < 2; mi++)
                    #pragma unroll
                    for (int s = 0; s < 2; s++) {
                        float* c = accg[mi][nj * 2 + s];
                        mma_bf16(c, ah[mi], bh[2 * s], bh[2 * s + 1]);
                        mma_bf16(c, ah[mi], bl[2 * s], bl[2 * s + 1]);
                        mma_bf16(c, al[mi], bh[2 * s], bh[2 * s + 1]);
                    }
            }
            if (DUAL) {
                #pragma unroll
                for (int nj = 0; nj < 2; nj++) {
                    unsigned bh[4], bl[4];
                    unsigned bd = b_addr + (2 * BTILE + kk * SB + nj * 16) * 2;
                    ldsm4t(bh, bd);
                    ldsm4t(bl, bd + BTILE * 2);
                    #pragma unroll
                    for (int mi = 0; mi < 2; mi++)
                        #pragma unroll
                        for (int s = 0; s < 2; s++) {
                            float* c = accu[mi][nj * 2 + s];
                            mma_bf16(c, ah[mi], bh[2 * s], bh[2 * s + 1]);
                            mma_bf16(c, ah[mi], bl[2 * s], bl[2 * s + 1]);
                            mma_bf16(c, al[mi], bh[2 * s], bh[2 * s + 1]);
                        }
                }
            }
        }
    }

    // ----- epilogue -----
    const int g  = lane >> 2;
    const int t4 = lane & 3;
    #pragma unroll
    for (int mi = 0; mi < 2; mi++) {
        #pragma unroll
        for (int nc = 0; nc < 4; nc++) {
            int col = n0 + wn * 32 + nc * 8 + t4 * 2;
            #pragma unroll
            for (int h = 0; h < 2; h++) {
                int m = m0 + wm * 32 + mi * 16 + g + h * 8;
                if (m >= M) continue;
                float c0 = accg[mi][nc][h * 2];
                float c1 = accg[mi][nc][h * 2 + 1];
                if (DUAL) {
                    float u0 = accu[mi][nc][h * 2];
                    float u1 = accu[mi][nc][h * 2 + 1];
                    float v0 = c0 / (1.f + __expf(-c0)) * u0;
                    float v1 = c1 / (1.f + __expf(-c1)) * u1;
                    *(float2*)(C + (size_t)m * NDIM + col) = make_float2(v0, v1);
                } else if (SCATTER) {
                    float w = g_wt[e * CAP + m];
                    float* o = C + (size_t)toks[m] * NDIM + col;
                    atomicAdd(o, c0 * w);
                    atomicAdd(o + 1, c1 * w);
                } else {
                    *(float2*)(C + (size_t)m * NDIM + col) = make_float2(c0, c1);
                }
            }
        }
    }
}

// ---------------- launch ----------------
extern "C" void kernel_launch(void* const* d_in, const int* in_sizes, int n_in,
                              void* d_out, int out_size) {
    const float* x       = (const float*)d_in[0];
    const float* gate_w  = (const float*)d_in[1];
    const float* bias    = (const float*)d_in[2];
    const float* w_gate  = (const float*)d_in[3];
    const float* w_up    = (const float*)d_in[4];
    const float* w_down  = (const float*)d_in[5];
    const float* ws_gate = (const float*)d_in[6];
    const float* ws_up   = (const float*)d_in[7];
    const float* ws_down = (const float*)d_in[8];
    float* out = (float*)d_out;

    float* tmp;  cudaGetSymbolAddress((void**)&tmp,  g_tmp);
    float* hbuf; cudaGetSymbolAddress((void**)&hbuf, g_hbuf);

    cudaFuncSetAttribute(mma_gemm<false, true,  H_DIM, F_DIM>,
                         cudaFuncAttributeMaxDynamicSharedMemorySize, SMEM_DUAL_BYTES);
    cudaFuncSetAttribute(mma_gemm<false, false, F_DIM, H_DIM>,
                         cudaFuncAttributeMaxDynamicSharedMemorySize, SMEM_SINGLE_BYTES);
    cudaFuncSetAttribute(mma_gemm<true,  true,  H_DIM, F_DIM>,
                         cudaFuncAttributeMaxDynamicSharedMemorySize, SMEM_DUAL_BYTES);
    cudaFuncSetAttribute(mma_gemm<true,  false, F_DIM, H_DIM>,
                         cudaFuncAttributeMaxDynamicSharedMemorySize, SMEM_SINGLE_BYTES);

    zero_cnt_kernel<<<1, 64>>>();
    router_kernel<<<T_TOK, 256>>>(x, gate_w, bias);

    // shared expert (plain stores initialize d_out)
    mma_gemm<false, true, H_DIM, F_DIM>
        <<<dim3(F_DIM / BN, T_TOK / BM, 1), NTHREADS, SMEM_DUAL_BYTES>>>(
            x, ws_gate, ws_up, tmp);
    mma_gemm<false, false, F_DIM, H_DIM>
        <<<dim3(H_DIM / BN, T_TOK / BM, 1), NTHREADS, SMEM_SINGLE_BYTES>>>(
            tmp, ws_down, nullptr, out);

    // routed experts
    mma_gemm<true, true, H_DIM, F_DIM>
        <<<dim3(F_DIM / BN, (CAP + BM - 1) / BM, E_NUM), NTHREADS, SMEM_DUAL_BYTES>>>(
            x, w_gate, w_up, hbuf);
    mma_gemm<true, false, F_DIM, H_DIM>
        <<<dim3(H_DIM / BN, (CAP + BM - 1) / BM, E_NUM), NTHREADS, SMEM_SINGLE_BYTES>>>(
            hbuf, w_down, nullptr, out);
}

// round 5
// speedup vs baseline: 1.8981x; 1.0003x over previous
#include <cuda_runtime.h>
#include <cuda_bf16.h>
#include <math.h>

#define T_TOK 2048
#define H_DIM 2048
#define E_NUM 64
#define TOPK 6
#define F_DIM 768
#define G_NUM 8
#define GSZ 8
#define KG_NUM 4
#define CAP 384
#define SCALEF 2.5f

// GEMM tile config
#define BM 256
#define BN 64
#define BK 32
#define NTHREADS 512

// smem layout (element offsets, bf16) within ONE buffer
#define SA 40                     // A row stride
#define SB 72                     // B row stride
#define OFF_ALO   (BM * SA)               // 10240
#define OFF_B     (2 * BM * SA)           // 20480  (B matrices start)
#define BTILE     (BK * SB)               // 2304
#define BUFE_DUAL   (OFF_B + 4 * BTILE)   // 29696 elems
#define BUFE_SINGLE (OFF_B + 2 * BTILE)   // 25088 elems
#define SMEM_DUAL_BYTES   (2 * BUFE_DUAL * 2)
#define SMEM_SINGLE_BYTES (2 * BUFE_SINGLE * 2)

// ---------------- device scratch ----------------
__device__ int   g_cnt[E_NUM];
__device__ int   g_tok[E_NUM * CAP];
__device__ float g_wt [E_NUM * CAP];
__device__ float g_hbuf[(size_t)E_NUM * CAP * F_DIM];
__device__ float g_tmp [(size_t)T_TOK * F_DIM];

// ---------------- helpers ----------------
__device__ __forceinline__ void ldsm4(unsigned r[4], unsigned addr) {
    asm volatile("ldmatrix.sync.aligned.m8n8.x4.shared.b16 {%0,%1,%2,%3}, [%4];\n"
        : "=r"(r[0]), "=r"(r[1]), "=r"(r[2]), "=r"(r[3]) : "r"(addr));
}
__device__ __forceinline__ void ldsm4t(unsigned r[4], unsigned addr) {
    asm volatile("ldmatrix.sync.aligned.m8n8.x4.trans.shared.b16 {%0,%1,%2,%3}, [%4];\n"
        : "=r"(r[0]), "=r"(r[1]), "=r"(r[2]), "=r"(r[3]) : "r"(addr));
}
__device__ __forceinline__ void mma_bf16(float c[4], const unsigned a[4],
                                         unsigned b0, unsigned b1) {
    asm volatile(
        "mma.sync.aligned.m16n8k16.row.col.f32.bf16.bf16.f32 "
        "{%0,%1,%2,%3},{%4,%5,%6,%7},{%8,%9},{%0,%1,%2,%3};\n"
        : "+f"(c[0]), "+f"(c[1]), "+f"(c[2]), "+f"(c[3])
        : "r"(a[0]), "r"(a[1]), "r"(a[2]), "r"(a[3]), "r"(b0), "r"(b1));
}

__device__ __forceinline__ void split_store(__nv_bfloat16* hi, __nv_bfloat16* lo,
                                            int off, float4 v) {
    __nv_bfloat16 h0 = __float2bfloat16_rn(v.x);
    __nv_bfloat16 h1 = __float2bfloat16_rn(v.y);
    __nv_bfloat16 h2 = __float2bfloat16_rn(v.z);
    __nv_bfloat16 h3 = __float2bfloat16_rn(v.w);
    __nv_bfloat16 l0 = __float2bfloat16_rn(v.x - __bfloat162float(h0));
    __nv_bfloat16 l1 = __float2bfloat16_rn(v.y - __bfloat162float(h1));
    __nv_bfloat16 l2 = __float2bfloat16_rn(v.z - __bfloat162float(h2));
    __nv_bfloat16 l3 = __float2bfloat16_rn(v.w - __bfloat162float(h3));
    union { __nv_bfloat16 b[4]; uint2 u; } H, L;
    H.b[0] = h0; H.b[1] = h1; H.b[2] = h2; H.b[3] = h3;
    L.b[0] = l0; L.b[1] = l1; L.b[2] = l2; L.b[3] = l3;
    *(uint2*)(hi + off) = H.u;
    *(uint2*)(lo + off) = L.u;
}

// ---------------- small kernels ----------------
__global__ void zero_cnt_kernel() {
    if (threadIdx.x < E_NUM) g_cnt[threadIdx.x] = 0;
}

__global__ void router_kernel(const float* __restrict__ x,
                              const float* __restrict__ gw,
                              const float* __restrict__ bias) {
    int t = blockIdx.x;
    int tid = threadIdx.x;
    int e = tid & 63, part = tid >> 6;
    __shared__ float ps[4][E_NUM];
    __shared__ float sc[E_NUM];
    __shared__ float scb[E_NUM];

    const float* xr = x + (size_t)t * H_DIM;
    float acc = 0.f;
    int h0 = part * (H_DIM / 4);
    #pragma unroll 4
    for (int h = 0; h < H_DIM / 4; h++)
        acc += xr[h0 + h] * gw[(size_t)(h0 + h) * E_NUM + e];
    ps[part][e] = acc;
    __syncthreads();

    if (tid < E_NUM) {
        float l = ps[0][e] + ps[1][e] + ps[2][e] + ps[3][e];
        float s = 1.f / (1.f + __expf(-l));
        sc[e] = s;
        scb[e] = s + bias[e];
    }
    __syncthreads();

    if (tid == 0) {
        float gsc[G_NUM];
        for (int g = 0; g < G_NUM; g++) {
            float m1 = -1e30f, m2 = -1e30f;
            for (int i = 0; i < GSZ; i++) {
                float v = scb[g * GSZ + i];
                if (v > m1) { m2 = m1; m1 = v; }
                else if (v > m2) { m2 = v; }
            }
            gsc[g] = m1 + m2;
        }
        bool gsel[G_NUM];
        for (int g = 0; g < G_NUM; g++) gsel[g] = false;
        for (int r = 0; r < KG_NUM; r++) {
            int bi = -1; float bv = -1e30f;
            for (int g = 0; g < G_NUM; g++)
                if (!gsel[g] && gsc[g] > bv) { bv = gsc[g]; bi = g; }
            gsel[bi] = true;
        }
        bool esel[E_NUM];
        for (int i = 0; i < E_NUM; i++) esel[i] = false;
        int ids[TOPK]; float ws[TOPK]; float wsum = 0.f;
        for (int r = 0; r < TOPK; r++) {
            int bi = -1; float bv = -1e30f;
            for (int ee = 0; ee < E_NUM; ee++) {
                if (!gsel[ee / GSZ] || esel[ee]) continue;
                float v = scb[ee];
                if (v > bv) { bv = v; bi = ee; }
            }
            esel[bi] = true; ids[r] = bi; ws[r] = sc[bi]; wsum += sc[bi];
        }
        float inv = SCALEF / wsum;
        for (int r = 0; r < TOPK; r++) {
            int ee = ids[r];
            int slot = atomicAdd(&g_cnt[ee], 1);
            if (slot < CAP) {
                g_tok[ee * CAP + slot] = t;
                g_wt [ee * CAP + slot] = ws[r] * inv;
            }
        }
    }
}

// ---------------- tensor-core GEMM (double-buffered) ----------------
template<bool EXPERT, bool DUAL, int KDIM, int NDIM>
__global__ __launch_bounds__(NTHREADS, 1)
void mma_gemm(const float* __restrict__ Abase,
              const float* __restrict__ W0base,
              const float* __restrict__ W1base,
              float* __restrict__ Cbase) {
    constexpr bool GATHER  = EXPERT && DUAL;
    constexpr bool SCATTER = EXPERT && !DUAL;
    constexpr int  BUFE    = DUAL ? BUFE_DUAL : BUFE_SINGLE;

    const int e = EXPERT ? blockIdx.z : 0;
    const int M = EXPERT ? min(g_cnt[e], CAP) : T_TOK;
    const int m0 = blockIdx.y * BM;
    if (m0 >= M) return;
    const int n0 = blockIdx.x * BN;

    const int* toks = EXPERT ? (g_tok + e * CAP) : nullptr;
    const float* A  = GATHER ? Abase
                             : (EXPERT ? Abase + (size_t)e * CAP * KDIM : Abase);
    const float* W0 = EXPERT ? W0base + (size_t)e * KDIM * NDIM : W0base;
    const float* W1 = nullptr;
    if (DUAL) W1 = EXPERT ? W1base + (size_t)e * KDIM * NDIM : W1base;
    float* C = DUAL ? (EXPERT ? Cbase + (size_t)e * CAP * NDIM : Cbase) : Cbase;

    extern __shared__ char smem_raw[];
    __nv_bfloat16* sm = (__nv_bfloat16*)smem_raw;

    const int tid  = threadIdx.x;
    const int lane = tid & 31;
    const int wid  = tid >> 5;
    const int wm = wid & 7;     // 8 warp rows (32 m each)
    const int wn = wid >> 3;    // 2 warp cols (32 n each)

    // ----- staging assignments -----
    const float* aptr[4];
    int aoffs[4];
    #pragma unroll
    for (int i = 0; i < 4; i++) {
        int idx = tid + i * NTHREADS;
        int row = idx >> 3;              // 0..255
        int c4  = (idx & 7) * 4;
        aoffs[i] = row * SA + c4;
        int gr = m0 + row;
        if (GATHER) {
            int tk = (gr < M) ? toks[gr] : toks[0];
            aptr[i] = A + (size_t)tk * KDIM + c4;
        } else {
            int r = (gr < M) ? gr : (M - 1);
            aptr[i] = A + (size_t)r * KDIM + c4;
        }
    }
    const int brow = tid >> 4;           // 0..31
    const int bc4  = (tid & 15) * 4;
    const int boffs = brow * SB + bc4;
    const float* bptr0 = W0 + (size_t)brow * NDIM + n0 + bc4;
    const float* bptr1 = DUAL ? (W1 + (size_t)brow * NDIM + n0 + bc4) : nullptr;

    // ----- ldmatrix addresses (relative to buffer start) -----
    unsigned sbase = (unsigned)__cvta_generic_to_shared(smem_raw);
    const int ar  = lane & 15;
    const int ac8 = (lane >> 4) * 8;
    unsigned a_rel = ((wm * 32 + ar) * SA + ac8) * 2;
    unsigned b_rel = (OFF_B + (lane & 15) * SB + wn * 32 + ac8) * 2;

    float accg[2][4][4] = {};
    float accu[2][4][4] = {};

    // prefetch registers
    float4 avr[4];
    float4 bvr0, bvr1;

    // prologue: load tile 0
    #pragma unroll
    for (int i = 0; i < 4; i++) avr[i] = *(const float4*)(aptr[i]);
    bvr0 = *(const float4*)(bptr0);
    if (DUAL) bvr1 = *(const float4*)(bptr1);

    constexpr int NIT = KDIM / BK;
    #pragma unroll 1
    for (int it = 0; it < NIT; it++) {
        const int bufo = (it & 1) ? BUFE : 0;
        __nv_bfloat16* Ahi  = sm + bufo;
        __nv_bfloat16* Alo  = Ahi + OFF_ALO;
        __nv_bfloat16* B0hi = sm + bufo + OFF_B;
        __nv_bfloat16* B0lo = B0hi + BTILE;

        // STS current prefetch
        #pragma unroll
        for (int i = 0; i < 4; i++) split_store(Ahi, Alo, aoffs[i], avr[i]);
        split_store(B0hi, B0lo, boffs, bvr0);
        if (DUAL) split_store(B0hi + 2 * BTILE, B0lo + 2 * BTILE, boffs, bvr1);

        // LDG next tile
        if (it + 1 < NIT) {
            const int k = (it + 1) * BK;
            #pragma unroll
            for (int i = 0; i < 4; i++) avr[i] = *(const float4*)(aptr[i] + k);
            bvr0 = *(const float4*)(bptr0 + (size_t)k * NDIM);
            if (DUAL) bvr1 = *(const float4*)(bptr1 + (size_t)k * NDIM);
        }
        __syncthreads();

        // compute on this buffer
        const unsigned a_addr = sbase + bufo * 2 + a_rel;
        const unsigned b_addr = sbase + bufo * 2 + b_rel;
        #pragma unroll
        for (int kk = 0; kk < BK; kk += 16) {
            unsigned ah[2][4], al[2][4];
            #pragma unroll
            for (int mi = 0; mi < 2; mi++) {
                unsigned ad = a_addr + (mi * 16 * SA + kk) * 2;
                ldsm4(ah[mi], ad);
                ldsm4(al[mi], ad + OFF_ALO * 2);
            }
            #pragma unroll
            for (int nj = 0; nj < 2; nj++) {
                unsigned bh[4], bl[4];
                unsigned bd = b_addr + (kk * SB + nj * 16) * 2;
                ldsm4t(bh, bd);
                ldsm4t(bl, bd + BTILE * 2);
                #pragma unroll
                for (int mi = 0; mi < 2; mi++)
                    #pragma unroll
                    for (int s = 0; s < 2; s++) {
                        float* c = accg[mi][nj * 2 + s];
                        mma_bf16(c, ah[mi], bh[2 * s], bh[2 * s + 1]);
                        mma_bf16(c, ah[mi], bl[2 * s], bl[2 * s + 1]);
                        mma_bf16(c, al[mi], bh[2 * s], bh[2 * s + 1]);
                    }
            }
            if (DUAL) {
                #pragma unroll
                for (int nj = 0; nj < 2; nj++) {
                    unsigned bh[4], bl[4];
                    unsigned bd = b_addr + (2 * BTILE + kk * SB + nj * 16) * 2;
                    ldsm4t(bh, bd);
                    ldsm4t(bl, bd + BTILE * 2);
                    #pragma unroll
                    for (int mi = 0; mi < 2; mi++)
                        #pragma unroll
                        for (int s = 0; s < 2; s++) {
                            float* c = accu[mi][nj * 2 + s];
                            mma_bf16(c, ah[mi], bh[2 * s], bh[2 * s + 1]);
                            mma_bf16(c, ah[mi], bl[2 * s], bl[2 * s + 1]);
                            mma_bf16(c, al[mi], bh[2 * s], bh[2 * s + 1]);
                        }
                }
            }
        }
    }

    // ----- epilogue -----
    const int g  = lane >> 2;
    const int t4 = lane & 3;
    #pragma unroll
    for (int mi = 0; mi < 2; mi++) {
        #pragma unroll
        for (int nc = 0; nc < 4; nc++) {
            int col = n0 + wn * 32 + nc * 8 + t4 * 2;
            #pragma unroll
            for (int h = 0; h < 2; h++) {
                int m = m0 + wm * 32 + mi * 16 + g + h * 8;
                if (m >= M) continue;
                float c0 = accg[mi][nc][h * 2];
                float c1 = accg[mi][nc][h * 2 + 1];
                if (DUAL) {
                    float u0 = accu[mi][nc][h * 2];
                    float u1 = accu[mi][nc][h * 2 + 1];
                    float v0 = c0 / (1.f + __expf(-c0)) * u0;
                    float v1 = c1 / (1.f + __expf(-c1)) * u1;
                    *(float2*)(C + (size_t)m * NDIM + col) = make_float2(v0, v1);
                } else if (SCATTER) {
                    float w = g_wt[e * CAP + m];
                    float* o = C + (size_t)toks[m] * NDIM + col;
                    atomicAdd(o, c0 * w);
                    atomicAdd(o + 1, c1 * w);
                } else {
                    *(float2*)(C + (size_t)m * NDIM + col) = make_float2(c0, c1);
                }
            }
        }
    }
}

// ---------------- launch ----------------
extern "C" void kernel_launch(void* const* d_in, const int* in_sizes, int n_in,
                              void* d_out, int out_size) {
    const float* x       = (const float*)d_in[0];
    const float* gate_w  = (const float*)d_in[1];
    const float* bias    = (const float*)d_in[2];
    const float* w_gate  = (const float*)d_in[3];
    const float* w_up    = (const float*)d_in[4];
    const float* w_down  = (const float*)d_in[5];
    const float* ws_gate = (const float*)d_in[6];
    const float* ws_up   = (const float*)d_in[7];
    const float* ws_down = (const float*)d_in[8];
    float* out = (float*)d_out;

    float* tmp;  cudaGetSymbolAddress((void**)&tmp,  g_tmp);
    float* hbuf; cudaGetSymbolAddress((void**)&hbuf, g_hbuf);

    cudaFuncSetAttribute(mma_gemm<false, true,  H_DIM, F_DIM>,
                         cudaFuncAttributeMaxDynamicSharedMemorySize, SMEM_DUAL_BYTES);
    cudaFuncSetAttribute(mma_gemm<false, false, F_DIM, H_DIM>,
                         cudaFuncAttributeMaxDynamicSharedMemorySize, SMEM_SINGLE_BYTES);
    cudaFuncSetAttribute(mma_gemm<true,  true,  H_DIM, F_DIM>,
                         cudaFuncAttributeMaxDynamicSharedMemorySize, SMEM_DUAL_BYTES);
    cudaFuncSetAttribute(mma_gemm<true,  false, F_DIM, H_DIM>,
                         cudaFuncAttributeMaxDynamicSharedMemorySize, SMEM_SINGLE_BYTES);

    zero_cnt_kernel<<<1, 64>>>();
    router_kernel<<<T_TOK, 256>>>(x, gate_w, bias);

    // shared expert (plain stores initialize d_out)
    mma_gemm<false, true, H_DIM, F_DIM>
        <<<dim3(F_DIM / BN, T_TOK / BM, 1), NTHREADS, SMEM_DUAL_BYTES>>>(
            x, ws_gate, ws_up, tmp);
    mma_gemm<false, false, F_DIM, H_DIM>
        <<<dim3(H_DIM / BN, T_TOK / BM, 1), NTHREADS, SMEM_SINGLE_BYTES>>>(
            tmp, ws_down, nullptr, out);

    // routed experts
    mma_gemm<true, true, H_DIM, F_DIM>
        <<<dim3(F_DIM / BN, (CAP + BM - 1) / BM, E_NUM), NTHREADS, SMEM_DUAL_BYTES>>>(
            x, w_gate, w_up, hbuf);
    mma_gemm<true, false, F_DIM, H_DIM>
        <<<dim3(H_DIM / BN, (CAP + BM - 1) / BM, E_NUM), NTHREADS, SMEM_SINGLE_BYTES>>>(
            hbuf, w_down, nullptr, out);
}

// round 7
// speedup vs baseline: 2.0812x; 1.0965x over previous
#include <cuda_runtime.h>
#include <cuda_bf16.h>
#include <math.h>

#define T_TOK 2048
#define H_DIM 2048
#define E_NUM 64
#define TOPK 6
#define F_DIM 768
#define G_NUM 8
#define GSZ 8
#define KG_NUM 4
#define CAP 384
#define SCALEF 2.5f

// GEMM tile config
#define BM 128
#define BN 64
#define BK 32
#define NTHREADS 256

// smem layout (element offsets, bf16) within ONE buffer
#define SA 40                     // A row stride
#define SB 72                     // B row stride
#define OFF_ALO   (BM * SA)               // 5120
#define OFF_B     (2 * BM * SA)           // 10240
#define BTILE     (BK * SB)               // 2304
#define BUFE_DUAL   (OFF_B + 4 * BTILE)   // 19456 elems
#define BUFE_SINGLE (OFF_B + 2 * BTILE)   // 14848 elems
#define SMEM_DUAL_BYTES   (2 * BUFE_DUAL * 2)
#define SMEM_SINGLE_BYTES (2 * BUFE_SINGLE * 2)

// ---------------- device scratch ----------------
__device__ int   g_cnt[E_NUM];
__device__ int   g_tok[E_NUM * CAP];
__device__ float g_wt [E_NUM * CAP];
__device__ float g_hbuf[(size_t)E_NUM * CAP * F_DIM];
__device__ float g_tmp [(size_t)T_TOK * F_DIM];

// ---------------- helpers ----------------
__device__ __forceinline__ void ldsm4(unsigned r[4], unsigned addr) {
    asm volatile("ldmatrix.sync.aligned.m8n8.x4.shared.b16 {%0,%1,%2,%3}, [%4];\n"
        : "=r"(r[0]), "=r"(r[1]), "=r"(r[2]), "=r"(r[3]) : "r"(addr));
}
__device__ __forceinline__ void ldsm4t(unsigned r[4], unsigned addr) {
    asm volatile("ldmatrix.sync.aligned.m8n8.x4.trans.shared.b16 {%0,%1,%2,%3}, [%4];\n"
        : "=r"(r[0]), "=r"(r[1]), "=r"(r[2]), "=r"(r[3]) : "r"(addr));
}
__device__ __forceinline__ void mma_bf16(float c[4], const unsigned a[4],
                                         unsigned b0, unsigned b1) {
    asm volatile(
        "mma.sync.aligned.m16n8k16.row.col.f32.bf16.bf16.f32 "
        "{%0,%1,%2,%3},{%4,%5,%6,%7},{%8,%9},{%0,%1,%2,%3};\n"
        : "+f"(c[0]), "+f"(c[1]), "+f"(c[2]), "+f"(c[3])
        : "r"(a[0]), "r"(a[1]), "r"(a[2]), "r"(a[3]), "r"(b0), "r"(b1));
}

__device__ __forceinline__ void split_store(__nv_bfloat16* hi, __nv_bfloat16* lo,
                                            int off, float4 v) {
    __nv_bfloat16 h0 = __float2bfloat16_rn(v.x);
    __nv_bfloat16 h1 = __float2bfloat16_rn(v.y);
    __nv_bfloat16 h2 = __float2bfloat16_rn(v.z);
    __nv_bfloat16 h3 = __float2bfloat16_rn(v.w);
    __nv_bfloat16 l0 = __float2bfloat16_rn(v.x - __bfloat162float(h0));
    __nv_bfloat16 l1 = __float2bfloat16_rn(v.y - __bfloat162float(h1));
    __nv_bfloat16 l2 = __float2bfloat16_rn(v.z - __bfloat162float(h2));
    __nv_bfloat16 l3 = __float2bfloat16_rn(v.w - __bfloat162float(h3));
    union { __nv_bfloat16 b[4]; uint2 u; } H, L;
    H.b[0] = h0; H.b[1] = h1; H.b[2] = h2; H.b[3] = h3;
    L.b[0] = l0; L.b[1] = l1; L.b[2] = l2; L.b[3] = l3;
    *(uint2*)(hi + off) = H.u;
    *(uint2*)(lo + off) = L.u;
}

// ---------------- small kernels ----------------
__global__ void zero_cnt_kernel() {
    if (threadIdx.x < E_NUM) g_cnt[threadIdx.x] = 0;
}

__global__ void router_kernel(const float* __restrict__ x,
                              const float* __restrict__ gw,
                              const float* __restrict__ bias) {
    int t = blockIdx.x;
    int tid = threadIdx.x;
    int e = tid & 63, part = tid >> 6;
    __shared__ float ps[4][E_NUM];
    __shared__ float sc[E_NUM];
    __shared__ float scb[E_NUM];

    const float* xr = x + (size_t)t * H_DIM;
    float acc = 0.f;
    int h0 = part * (H_DIM / 4);
    #pragma unroll 4
    for (int h = 0; h < H_DIM / 4; h++)
        acc += xr[h0 + h] * gw[(size_t)(h0 + h) * E_NUM + e];
    ps[part][e] = acc;
    __syncthreads();

    if (tid < E_NUM) {
        float l = ps[0][e] + ps[1][e] + ps[2][e] + ps[3][e];
        float s = 1.f / (1.f + __expf(-l));
        sc[e] = s;
        scb[e] = s + bias[e];
    }
    __syncthreads();

    if (tid == 0) {
        float gsc[G_NUM];
        for (int g = 0; g < G_NUM; g++) {
            float m1 = -1e30f, m2 = -1e30f;
            for (int i = 0; i < GSZ; i++) {
                float v = scb[g * GSZ + i];
                if (v > m1) { m2 = m1; m1 = v; }
                else if (v > m2) { m2 = v; }
            }
            gsc[g] = m1 + m2;
        }
        bool gsel[G_NUM];
        for (int g = 0; g < G_NUM; g++) gsel[g] = false;
        for (int r = 0; r < KG_NUM; r++) {
            int bi = -1; float bv = -1e30f;
            for (int g = 0; g < G_NUM; g++)
                if (!gsel[g] && gsc[g] > bv) { bv = gsc[g]; bi = g; }
            gsel[bi] = true;
        }
        bool esel[E_NUM];
        for (int i = 0; i < E_NUM; i++) esel[i] = false;
        int ids[TOPK]; float ws[TOPK]; float wsum = 0.f;
        for (int r = 0; r < TOPK; r++) {
            int bi = -1; float bv = -1e30f;
            for (int ee = 0; ee < E_NUM; ee++) {
                if (!gsel[ee / GSZ] || esel[ee]) continue;
                float v = scb[ee];
                if (v > bv) { bv = v; bi = ee; }
            }
            esel[bi] = true; ids[r] = bi; ws[r] = sc[bi]; wsum += sc[bi];
        }
        float inv = SCALEF / wsum;
        for (int r = 0; r < TOPK; r++) {
            int ee = ids[r];
            int slot = atomicAdd(&g_cnt[ee], 1);
            if (slot < CAP) {
                g_tok[ee * CAP + slot] = t;
                g_wt [ee * CAP + slot] = ws[r] * inv;
            }
        }
    }
}

// ---------------- tensor-core GEMM (double-buffered, 2 CTA/SM) ----------------
template<bool EXPERT, bool DUAL, int KDIM, int NDIM>
__global__ __launch_bounds__(NTHREADS, 2)
void mma_gemm(const float* __restrict__ Abase,
              const float* __restrict__ W0base,
              const float* __restrict__ W1base,
              float* __restrict__ Cbase) {
    constexpr bool GATHER  = EXPERT && DUAL;
    constexpr bool SCATTER = EXPERT && !DUAL;
    constexpr int  BUFE    = DUAL ? BUFE_DUAL : BUFE_SINGLE;

    const int e = EXPERT ? blockIdx.z : 0;
    const int M = EXPERT ? min(g_cnt[e], CAP) : T_TOK;
    const int m0 = blockIdx.y * BM;
    if (m0 >= M) return;
    const int n0 = blockIdx.x * BN;

    const int* toks = EXPERT ? (g_tok + e * CAP) : nullptr;
    const float* A  = GATHER ? Abase
                             : (EXPERT ? Abase + (size_t)e * CAP * KDIM : Abase);
    const float* W0 = EXPERT ? W0base + (size_t)e * KDIM * NDIM : W0base;
    const float* W1 = nullptr;
    if (DUAL) W1 = EXPERT ? W1base + (size_t)e * KDIM * NDIM : W1base;
    float* C = DUAL ? (EXPERT ? Cbase + (size_t)e * CAP * NDIM : Cbase) : Cbase;

    extern __shared__ char smem_raw[];
    __nv_bfloat16* sm = (__nv_bfloat16*)smem_raw;

    const int tid  = threadIdx.x;
    const int lane = tid & 31;
    const int wid  = tid >> 5;
    const int wm = wid & 3;     // 4 warp rows (32 m each)
    const int wn = wid >> 2;    // 2 warp cols (32 n each)

    // ----- staging assignments -----
    // A: 128x32 fp32 = 1024 float4 over 256 threads -> 4 each
    const float* aptr[4];
    int aoffs[4];
    #pragma unroll
    for (int i = 0; i < 4; i++) {
        int idx = tid + i * NTHREADS;
        int row = idx >> 3;              // 0..127
        int c4  = (idx & 7) * 4;
        aoffs[i] = row * SA + c4;
        int gr = m0 + row;
        if (GATHER) {
            int tk = (gr < M) ? toks[gr] : toks[0];
            aptr[i] = A + (size_t)tk * KDIM + c4;
        } else {
            int r = (gr < M) ? gr : (M - 1);
            aptr[i] = A + (size_t)r * KDIM + c4;
        }
    }
    // B: 32x64 fp32 = 512 float4 over 256 threads -> 2 each (per matrix)
    const float* bptr0[2];
    const float* bptr1[2];
    int boffs[2];
    #pragma unroll
    for (int i = 0; i < 2; i++) {
        int idx = tid + i * NTHREADS;
        int row = idx >> 4;              // 0..31
        int c4  = (idx & 15) * 4;
        boffs[i] = row * SB + c4;
        bptr0[i] = W0 + (size_t)row * NDIM + n0 + c4;
        if (DUAL) bptr1[i] = W1 + (size_t)row * NDIM + n0 + c4;
    }

    // ----- ldmatrix addresses (relative to buffer start) -----
    unsigned sbase = (unsigned)__cvta_generic_to_shared(smem_raw);
    const int ar  = lane & 15;
    const int ac8 = (lane >> 4) * 8;
    unsigned a_rel = ((wm * 32 + ar) * SA + ac8) * 2;
    unsigned b_rel = (OFF_B + (lane & 15) * SB + wn * 32 + ac8) * 2;

    float accg[2][4][4] = {};
    float accu[2][4][4] = {};

    // prefetch registers
    float4 avr[4];
    float4 bvr0[2], bvr1[2];

    // prologue: load tile 0
    #pragma unroll
    for (int i = 0; i < 4; i++) avr[i] = *(const float4*)(aptr[i]);
    #pragma unroll
    for (int i = 0; i < 2; i++) {
        bvr0[i] = *(const float4*)(bptr0[i]);
        if (DUAL) bvr1[i] = *(const float4*)(bptr1[i]);
    }

    constexpr int NIT = KDIM / BK;
    #pragma unroll 1
    for (int it = 0; it < NIT; it++) {
        const int bufo = (it & 1) ? BUFE : 0;
        __nv_bfloat16* Ahi  = sm + bufo;
        __nv_bfloat16* Alo  = Ahi + OFF_ALO;
        __nv_bfloat16* B0hi = sm + bufo + OFF_B;
        __nv_bfloat16* B0lo = B0hi + BTILE;

        // STS current prefetch
        #pragma unroll
        for (int i = 0; i < 4; i++) split_store(Ahi, Alo, aoffs[i], avr[i]);
        #pragma unroll
        for (int i = 0; i < 2; i++) {
            split_store(B0hi, B0lo, boffs[i], bvr0[i]);
            if (DUAL) split_store(B0hi + 2 * BTILE, B0lo + 2 * BTILE, boffs[i], bvr1[i]);
        }

        // LDG next tile
        if (it + 1 < NIT) {
            const int k = (it + 1) * BK;
            #pragma unroll
            for (int i = 0; i < 4; i++) avr[i] = *(const float4*)(aptr[i] + k);
            #pragma unroll
            for (int i = 0; i < 2; i++) {
                bvr0[i] = *(const float4*)(bptr0[i] + (size_t)k * NDIM);
                if (DUAL) bvr1[i] = *(const float4*)(bptr1[i] + (size_t)k * NDIM);
            }
        }
        __syncthreads();

        // compute on this buffer
        const unsigned a_addr = sbase + bufo * 2 + a_rel;
        const unsigned b_addr = sbase + bufo * 2 + b_rel;
        #pragma unroll
        for (int kk = 0; kk < BK; kk += 16) {
            unsigned ah[2][4], al[2][4];
            #pragma unroll
            for (int mi = 0; mi < 2; mi++) {
                unsigned ad = a_addr + (mi * 16 * SA + kk) * 2;
                ldsm4(ah[mi], ad);
                ldsm4(al[mi], ad + OFF_ALO * 2);
            }
            #pragma unroll
            for (int nj = 0; nj < 2; nj++) {
                unsigned bh[4], bl[4];
                unsigned bd = b_addr + (kk * SB + nj * 16) * 2;
                ldsm4t(bh, bd);
                ldsm4t(bl, bd + BTILE * 2);
                #pragma unroll
                for (int mi = 0; mi < 2; mi++)
                    #pragma unroll
                    for (int s = 0; s < 2; s++) {
                        float* c = accg[mi][nj * 2 + s];
                        mma_bf16(c, ah[mi], bh[2 * s], bh[2 * s + 1]);
                        mma_bf16(c, ah[mi], bl[2 * s], bl[2 * s + 1]);
                        mma_bf16(c, al[mi], bh[2 * s], bh[2 * s + 1]);
                    }
            }
            if (DUAL) {
                #pragma unroll
                for (int nj = 0; nj < 2; nj++) {
                    unsigned bh[4], bl[4];
                    unsigned bd = b_addr + (2 * BTILE + kk * SB + nj * 16) * 2;
                    ldsm4t(bh, bd);
                    ldsm4t(bl, bd + BTILE * 2);
                    #pragma unroll
                    for (int mi = 0; mi < 2; mi++)
                        #pragma unroll
                        for (int s = 0; s < 2; s++) {
                            float* c = accu[mi][nj * 2 + s];
                            mma_bf16(c, ah[mi], bh[2 * s], bh[2 * s + 1]);
                            mma_bf16(c, ah[mi], bl[2 * s], bl[2 * s + 1]);
                            mma_bf16(c, al[mi], bh[2 * s], bh[2 * s + 1]);
                        }
                }
            }
        }
    }

    // ----- epilogue -----
    const int g  = lane >> 2;
    const int t4 = lane & 3;
    #pragma unroll
    for (int mi = 0; mi < 2; mi++) {
        #pragma unroll
        for (int nc = 0; nc < 4; nc++) {
            int col = n0 + wn * 32 + nc * 8 + t4 * 2;
            #pragma unroll
            for (int h = 0; h < 2; h++) {
                int m = m0 + wm * 32 + mi * 16 + g + h * 8;
                if (m >= M) continue;
                float c0 = accg[mi][nc][h * 2];
                float c1 = accg[mi][nc][h * 2 + 1];
                if (DUAL) {
                    float u0 = accu[mi][nc][h * 2];
                    float u1 = accu[mi][nc][h * 2 + 1];
                    float v0 = c0 / (1.f + __expf(-c0)) * u0;
                    float v1 = c1 / (1.f + __expf(-c1)) * u1;
                    *(float2*)(C + (size_t)m * NDIM + col) = make_float2(v0, v1);
                } else if (SCATTER) {
                    float w = g_wt[e * CAP + m];
                    float* o = C + (size_t)toks[m] * NDIM + col;
                    atomicAdd(o, c0 * w);
                    atomicAdd(o + 1, c1 * w);
                } else {
                    *(float2*)(C + (size_t)m * NDIM + col) = make_float2(c0, c1);
                }
            }
        }
    }
}

// ---------------- launch ----------------
extern "C" void kernel_launch(void* const* d_in, const int* in_sizes, int n_in,
                              void* d_out, int out_size) {
    const float* x       = (const float*)d_in[0];
    const float* gate_w  = (const float*)d_in[1];
    const float* bias    = (const float*)d_in[2];
    const float* w_gate  = (const float*)d_in[3];
    const float* w_up    = (const float*)d_in[4];
    const float* w_down  = (const float*)d_in[5];
    const float* ws_gate = (const float*)d_in[6];
    const float* ws_up   = (const float*)d_in[7];
    const float* ws_down = (const float*)d_in[8];
    float* out = (float*)d_out;

    float* tmp;  cudaGetSymbolAddress((void**)&tmp,  g_tmp);
    float* hbuf; cudaGetSymbolAddress((void**)&hbuf, g_hbuf);

    cudaFuncSetAttribute(mma_gemm<false, true,  H_DIM, F_DIM>,
                         cudaFuncAttributeMaxDynamicSharedMemorySize, SMEM_DUAL_BYTES);
    cudaFuncSetAttribute(mma_gemm<false, false, F_DIM, H_DIM>,
                         cudaFuncAttributeMaxDynamicSharedMemorySize, SMEM_SINGLE_BYTES);
    cudaFuncSetAttribute(mma_gemm<true,  true,  H_DIM, F_DIM>,
                         cudaFuncAttributeMaxDynamicSharedMemorySize, SMEM_DUAL_BYTES);
    cudaFuncSetAttribute(mma_gemm<true,  false, F_DIM, H_DIM>,
                         cudaFuncAttributeMaxDynamicSharedMemorySize, SMEM_SINGLE_BYTES);

    zero_cnt_kernel<<<1, 64>>>();
    router_kernel<<<T_TOK, 256>>>(x, gate_w, bias);

    // shared expert (plain stores initialize d_out)
    mma_gemm<false, true, H_DIM, F_DIM>
        <<<dim3(F_DIM / BN, T_TOK / BM, 1), NTHREADS, SMEM_DUAL_BYTES>>>(
            x, ws_gate, ws_up, tmp);
    mma_gemm<false, false, F_DIM, H_DIM>
        <<<dim3(H_DIM / BN, T_TOK / BM, 1), NTHREADS, SMEM_SINGLE_BYTES>>>(
            tmp, ws_down, nullptr, out);

    // routed experts
    mma_gemm<true, true, H_DIM, F_DIM>
        <<<dim3(F_DIM / BN, (CAP + BM - 1) / BM, E_NUM), NTHREADS, SMEM_DUAL_BYTES>>>(
            x, w_gate, w_up, hbuf);
    mma_gemm<true, false, F_DIM, H_DIM>
        <<<dim3(H_DIM / BN, (CAP + BM - 1) / BM, E_NUM), NTHREADS, SMEM_SINGLE_BYTES>>>(
            hbuf, w_down, nullptr, out);
}

// round 9
// speedup vs baseline: 2.8586x; 1.3735x over previous
#include <cuda_runtime.h>
#include <cuda_fp16.h>
#include <math.h>

#define T_TOK 2048
#define H_DIM 2048
#define E_NUM 64
#define TOPK 6
#define F_DIM 768
#define G_NUM 8
#define GSZ 8
#define KG_NUM 4
#define CAP 384
#define SCALEF 2.5f

// GEMM tile config
#define BM 128
#define BN 64
#define BK 32
#define NTHREADS 256

// smem layout (element offsets, fp16) within ONE buffer
#define SA 40                     // A row stride
#define SB 72                     // B row stride
#define OFF_ALO   (BM * SA)               // 5120
#define OFF_B     (2 * BM * SA)           // 10240
#define BTILE     (BK * SB)               // 2304
#define BUFE_DUAL   (OFF_B + 2 * BTILE)   // 14848 elems (B0, B1 single fp16)
#define BUFE_SINGLE (OFF_B + 1 * BTILE)   // 12544 elems
#define SMEM_DUAL_BYTES   (2 * BUFE_DUAL * 2)     // 59392
#define SMEM_SINGLE_BYTES (2 * BUFE_SINGLE * 2)   // 50176

// ---------------- device scratch ----------------
__device__ int   g_cnt[E_NUM];
__device__ int   g_tok[E_NUM * CAP];
__device__ float g_wt [E_NUM * CAP];
__device__ float g_hbuf[(size_t)E_NUM * CAP * F_DIM];
__device__ float g_tmp [(size_t)T_TOK * F_DIM];

// ---------------- helpers ----------------
__device__ __forceinline__ void ldsm4(unsigned r[4], unsigned addr) {
    asm volatile("ldmatrix.sync.aligned.m8n8.x4.shared.b16 {%0,%1,%2,%3}, [%4];\n"
        : "=r"(r[0]), "=r"(r[1]), "=r"(r[2]), "=r"(r[3]) : "r"(addr));
}
__device__ __forceinline__ void ldsm4t(unsigned r[4], unsigned addr) {
    asm volatile("ldmatrix.sync.aligned.m8n8.x4.trans.shared.b16 {%0,%1,%2,%3}, [%4];\n"
        : "=r"(r[0]), "=r"(r[1]), "=r"(r[2]), "=r"(r[3]) : "r"(addr));
}
__device__ __forceinline__ void mma_f16(float c[4], const unsigned a[4],
                                        unsigned b0, unsigned b1) {
    asm volatile(
        "mma.sync.aligned.m16n8k16.row.col.f32.f16.f16.f32 "
        "{%0,%1,%2,%3},{%4,%5,%6,%7},{%8,%9},{%0,%1,%2,%3};\n"
        : "+f"(c[0]), "+f"(c[1]), "+f"(c[2]), "+f"(c[3])
        : "r"(a[0]), "r"(a[1]), "r"(a[2]), "r"(a[3]), "r"(b0), "r"(b1));
}

// A: fp32 -> fp16 hi + fp16 lo (22-bit effective mantissa)
__device__ __forceinline__ void split_store_a(__half* hi, __half* lo,
                                              int off, float4 v) {
    __half h0 = __float2half_rn(v.x);
    __half h1 = __float2half_rn(v.y);
    __half h2 = __float2half_rn(v.z);
    __half h3 = __float2half_rn(v.w);
    __half l0 = __float2half_rn(v.x - __half2float(h0));
    __half l1 = __float2half_rn(v.y - __half2float(h1));
    __half l2 = __float2half_rn(v.z - __half2float(h2));
    __half l3 = __float2half_rn(v.w - __half2float(h3));
    union { __half b[4]; uint2 u; } H, L;
    H.b[0] = h0; H.b[1] = h1; H.b[2] = h2; H.b[3] = h3;
    L.b[0] = l0; L.b[1] = l1; L.b[2] = l2; L.b[3] = l3;
    *(uint2*)(hi + off) = H.u;
    *(uint2*)(lo + off) = L.u;
}
// B: fp32 -> fp16 (single)
__device__ __forceinline__ void store_b(__half* dst, int off, float4 v) {
    union { __half b[4]; uint2 u; } H;
    H.b[0] = __float2half_rn(v.x);
    H.b[1] = __float2half_rn(v.y);
    H.b[2] = __float2half_rn(v.z);
    H.b[3] = __float2half_rn(v.w);
    *(uint2*)(dst + off) = H.u;
}

// ---------------- small kernels ----------------
__global__ void zero_cnt_kernel() {
    if (threadIdx.x < E_NUM) g_cnt[threadIdx.x] = 0;
}

__global__ void router_kernel(const float* __restrict__ x,
                              const float* __restrict__ gw,
                              const float* __restrict__ bias) {
    int t = blockIdx.x;
    int tid = threadIdx.x;
    int e = tid & 63, part = tid >> 6;
    __shared__ float ps[4][E_NUM];
    __shared__ float sc[E_NUM];
    __shared__ float scb[E_NUM];

    const float* xr = x + (size_t)t * H_DIM;
    float acc = 0.f;
    int h0 = part * (H_DIM / 4);
    #pragma unroll 4
    for (int h = 0; h < H_DIM / 4; h++)
        acc += xr[h0 + h] * gw[(size_t)(h0 + h) * E_NUM + e];
    ps[part][e] = acc;
    __syncthreads();

    if (tid < E_NUM) {
        float l = ps[0][e] + ps[1][e] + ps[2][e] + ps[3][e];
        float s = 1.f / (1.f + __expf(-l));
        sc[e] = s;
        scb[e] = s + bias[e];
    }
    __syncthreads();

    if (tid == 0) {
        float gsc[G_NUM];
        for (int g = 0; g < G_NUM; g++) {
            float m1 = -1e30f, m2 = -1e30f;
            for (int i = 0; i < GSZ; i++) {
                float v = scb[g * GSZ + i];
                if (v > m1) { m2 = m1; m1 = v; }
                else if (v > m2) { m2 = v; }
            }
            gsc[g] = m1 + m2;
        }
        bool gsel[G_NUM];
        for (int g = 0; g < G_NUM; g++) gsel[g] = false;
        for (int r = 0; r < KG_NUM; r++) {
            int bi = -1; float bv = -1e30f;
            for (int g = 0; g < G_NUM; g++)
                if (!gsel[g] && gsc[g] > bv) { bv = gsc[g]; bi = g; }
            gsel[bi] = true;
        }
        bool esel[E_NUM];
        for (int i = 0; i < E_NUM; i++) esel[i] = false;
        int ids[TOPK]; float ws[TOPK]; float wsum = 0.f;
        for (int r = 0; r < TOPK; r++) {
            int bi = -1; float bv = -1e30f;
            for (int ee = 0; ee < E_NUM; ee++) {
                if (!gsel[ee / GSZ] || esel[ee]) continue;
                float v = scb[ee];
                if (v > bv) { bv = v; bi = ee; }
            }
            esel[bi] = true; ids[r] = bi; ws[r] = sc[bi]; wsum += sc[bi];
        }
        float inv = SCALEF / wsum;
        for (int r = 0; r < TOPK; r++) {
            int ee = ids[r];
            int slot = atomicAdd(&g_cnt[ee], 1);
            if (slot < CAP) {
                g_tok[ee * CAP + slot] = t;
                g_wt [ee * CAP + slot] = ws[r] * inv;
            }
        }
    }
}

// ---------------- tensor-core GEMM (fp16 hi/lo x2, double-buffered, 2 CTA/SM) --
template<bool EXPERT, bool DUAL, int KDIM, int NDIM>
__global__ __launch_bounds__(NTHREADS, 2)
void mma_gemm(const float* __restrict__ Abase,
              const float* __restrict__ W0base,
              const float* __restrict__ W1base,
              float* __restrict__ Cbase) {
    constexpr bool GATHER  = EXPERT && DUAL;
    constexpr bool SCATTER = EXPERT && !DUAL;
    constexpr int  BUFE    = DUAL ? BUFE_DUAL : BUFE_SINGLE;

    const int e = EXPERT ? blockIdx.z : 0;
    const int M = EXPERT ? min(g_cnt[e], CAP) : T_TOK;
    const int m0 = blockIdx.y * BM;
    if (m0 >= M) return;
    const int n0 = blockIdx.x * BN;

    const int* toks = EXPERT ? (g_tok + e * CAP) : nullptr;
    const float* A  = GATHER ? Abase
                             : (EXPERT ? Abase + (size_t)e * CAP * KDIM : Abase);
    const float* W0 = EXPERT ? W0base + (size_t)e * KDIM * NDIM : W0base;
    const float* W1 = nullptr;
    if (DUAL) W1 = EXPERT ? W1base + (size_t)e * KDIM * NDIM : W1base;
    float* C = DUAL ? (EXPERT ? Cbase + (size_t)e * CAP * NDIM : Cbase) : Cbase;

    extern __shared__ char smem_raw[];
    __half* sm = (__half*)smem_raw;

    const int tid  = threadIdx.x;
    const int lane = tid & 31;
    const int wid  = tid >> 5;
    const int wm = wid & 3;     // 4 warp rows (32 m each)
    const int wn = wid >> 2;    // 2 warp cols (32 n each)

    // ----- staging assignments -----
    // A: 128x32 fp32 = 1024 float4 over 256 threads -> 4 each
    const float* aptr[4];
    int aoffs[4];
    #pragma unroll
    for (int i = 0; i < 4; i++) {
        int idx = tid + i * NTHREADS;
        int row = idx >> 3;              // 0..127
        int c4  = (idx & 7) * 4;
        aoffs[i] = row * SA + c4;
        int gr = m0 + row;
        if (GATHER) {
            int tk = (gr < M) ? toks[gr] : toks[0];
            aptr[i] = A + (size_t)tk * KDIM + c4;
        } else {
            int r = (gr < M) ? gr : (M - 1);
            aptr[i] = A + (size_t)r * KDIM + c4;
        }
    }
    // B: 32x64 fp32 = 512 float4 over 256 threads -> 2 each (per matrix)
    const float* bptr0[2];
    const float* bptr1[2];
    int boffs[2];
    #pragma unroll
    for (int i = 0; i < 2; i++) {
        int idx = tid + i * NTHREADS;
        int row = idx >> 4;              // 0..31
        int c4  = (idx & 15) * 4;
        boffs[i] = row * SB + c4;
        bptr0[i] = W0 + (size_t)row * NDIM + n0 + c4;
        if (DUAL) bptr1[i] = W1 + (size_t)row * NDIM + n0 + c4;
    }

    // ----- ldmatrix addresses (relative to buffer start) -----
    unsigned sbase = (unsigned)__cvta_generic_to_shared(smem_raw);
    const int ar  = lane & 15;
    const int ac8 = (lane >> 4) * 8;
    unsigned a_rel = ((wm * 32 + ar) * SA + ac8) * 2;
    unsigned b_rel = (OFF_B + (lane & 15) * SB + wn * 32 + ac8) * 2;

    float accg[2][4][4] = {};
    float accu[2][4][4] = {};

    // prefetch registers
    float4 avr[4];
    float4 bvr0[2], bvr1[2];

    // prologue: load tile 0
    #pragma unroll
    for (int i = 0; i < 4; i++) avr[i] = *(const float4*)(aptr[i]);
    #pragma unroll
    for (int i = 0; i < 2; i++) {
        bvr0[i] = *(const float4*)(bptr0[i]);
        if (DUAL) bvr1[i] = *(const float4*)(bptr1[i]);
    }

    constexpr int NIT = KDIM / BK;
    #pragma unroll 1
    for (int it = 0; it < NIT; it++) {
        const int bufo = (it & 1) ? BUFE : 0;
        __half* Ahi = sm + bufo;
        __half* Alo = Ahi + OFF_ALO;
        __half* B0  = sm + bufo + OFF_B;
        __half* B1  = B0 + BTILE;

        // STS current prefetch
        #pragma unroll
        for (int i = 0; i < 4; i++) split_store_a(Ahi, Alo, aoffs[i], avr[i]);
        #pragma unroll
        for (int i = 0; i < 2; i++) {
            store_b(B0, boffs[i], bvr0[i]);
            if (DUAL) store_b(B1, boffs[i], bvr1[i]);
        }

        // LDG next tile
        if (it + 1 < NIT) {
            const int k = (it + 1) * BK;
            #pragma unroll
            for (int i = 0; i < 4; i++) avr[i] = *(const float4*)(aptr[i] + k);
            #pragma unroll
            for (int i = 0; i < 2; i++) {
                bvr0[i] = *(const float4*)(bptr0[i] + (size_t)k * NDIM);
                if (DUAL) bvr1[i] = *(const float4*)(bptr1[i] + (size_t)k * NDIM);
            }
        }
        __syncthreads();

        // compute on this buffer
        const unsigned a_addr = sbase + bufo * 2 + a_rel;
        const unsigned b_addr = sbase + bufo * 2 + b_rel;
        #pragma unroll
        for (int kk = 0; kk < BK; kk += 16) {
            unsigned ah[2][4], al[2][4];
            #pragma unroll
            for (int mi = 0; mi < 2; mi++) {
                unsigned ad = a_addr + (mi * 16 * SA + kk) * 2;
                ldsm4(ah[mi], ad);
                ldsm4(al[mi], ad + OFF_ALO * 2);
            }
            #pragma unroll
            for (int nj = 0; nj < 2; nj++) {
                unsigned bh[4];
                unsigned bd = b_addr + (kk * SB + nj * 16) * 2;
                ldsm4t(bh, bd);
                #pragma unroll
                for (int mi = 0; mi < 2; mi++)
                    #pragma unroll
                    for (int s = 0; s < 2; s++) {
                        float* c = accg[mi][nj * 2 + s];
                        mma_f16(c, ah[mi], bh[2 * s], bh[2 * s + 1]);
                        mma_f16(c, al[mi], bh[2 * s], bh[2 * s + 1]);
                    }
            }
            if (DUAL) {
                #pragma unroll
                for (int nj = 0; nj < 2; nj++) {
                    unsigned bh[4];
                    unsigned bd = b_addr + (BTILE + kk * SB + nj * 16) * 2;
                    ldsm4t(bh, bd);
                    #pragma unroll
                    for (int mi = 0; mi < 2; mi++)
                        #pragma unroll
                        for (int s = 0; s < 2; s++) {
                            float* c = accu[mi][nj * 2 + s];
                            mma_f16(c, ah[mi], bh[2 * s], bh[2 * s + 1]);
                            mma_f16(c, al[mi], bh[2 * s], bh[2 * s + 1]);
                        }
                }
            }
        }
    }

    // ----- epilogue -----
    const int g  = lane >> 2;
    const int t4 = lane & 3;
    #pragma unroll
    for (int mi = 0; mi < 2; mi++) {
        #pragma unroll
        for (int nc = 0; nc < 4; nc++) {
            int col = n0 + wn * 32 + nc * 8 + t4 * 2;
            #pragma unroll
            for (int h = 0; h < 2; h++) {
                int m = m0 + wm * 32 + mi * 16 + g + h * 8;
                if (m >= M) continue;
                float c0 = accg[mi][nc][h * 2];
                float c1 = accg[mi][nc][h * 2 + 1];
                if (DUAL) {
                    float u0 = accu[mi][nc][h * 2];
                    float u1 = accu[mi][nc][h * 2 + 1];
                    float v0 = c0 / (1.f + __expf(-c0)) * u0;
                    float v1 = c1 / (1.f + __expf(-c1)) * u1;
                    *(float2*)(C + (size_t)m * NDIM + col) = make_float2(v0, v1);
                } else if (SCATTER) {
                    float w = g_wt[e * CAP + m];
                    float* o = C + (size_t)toks[m] * NDIM + col;
                    atomicAdd(o, c0 * w);
                    atomicAdd(o + 1, c1 * w);
                } else {
                    *(float2*)(C + (size_t)m * NDIM + col) = make_float2(c0, c1);
                }
            }
        }
    }
}

// ---------------- launch ----------------
extern "C" void kernel_launch(void* const* d_in, const int* in_sizes, int n_in,
                              void* d_out, int out_size) {
    const float* x       = (const float*)d_in[0];
    const float* gate_w  = (const float*)d_in[1];
    const float* bias    = (const float*)d_in[2];
    const float* w_gate  = (const float*)d_in[3];
    const float* w_up    = (const float*)d_in[4];
    const float* w_down  = (const float*)d_in[5];
    const float* ws_gate = (const float*)d_in[6];
    const float* ws_up   = (const float*)d_in[7];
    const float* ws_down = (const float*)d_in[8];
    float* out = (float*)d_out;

    float* tmp;  cudaGetSymbolAddress((void**)&tmp,  g_tmp);
    float* hbuf; cudaGetSymbolAddress((void**)&hbuf, g_hbuf);

    cudaFuncSetAttribute(mma_gemm<false, true,  H_DIM, F_DIM>,
                         cudaFuncAttributeMaxDynamicSharedMemorySize, SMEM_DUAL_BYTES);
    cudaFuncSetAttribute(mma_gemm<false, false, F_DIM, H_DIM>,
                         cudaFuncAttributeMaxDynamicSharedMemorySize, SMEM_SINGLE_BYTES);
    cudaFuncSetAttribute(mma_gemm<true,  true,  H_DIM, F_DIM>,
                         cudaFuncAttributeMaxDynamicSharedMemorySize, SMEM_DUAL_BYTES);
    cudaFuncSetAttribute(mma_gemm<true,  false, F_DIM, H_DIM>,
                         cudaFuncAttributeMaxDynamicSharedMemorySize, SMEM_SINGLE_BYTES);

    zero_cnt_kernel<<<1, 64>>>();
    router_kernel<<<T_TOK, 256>>>(x, gate_w, bias);

    // shared expert (plain stores initialize d_out)
    mma_gemm<false, true, H_DIM, F_DIM>
        <<<dim3(F_DIM / BN, T_TOK / BM, 1), NTHREADS, SMEM_DUAL_BYTES>>>(
            x, ws_gate, ws_up, tmp);
    mma_gemm<false, false, F_DIM, H_DIM>
        <<<dim3(H_DIM / BN, T_TOK / BM, 1), NTHREADS, SMEM_SINGLE_BYTES>>>(
            tmp, ws_down, nullptr, out);

    // routed experts
    mma_gemm<true, true, H_DIM, F_DIM>
        <<<dim3(F_DIM / BN, (CAP + BM - 1) / BM, E_NUM), NTHREADS, SMEM_DUAL_BYTES>>>(
            x, w_gate, w_up, hbuf);
    mma_gemm<true, false, F_DIM, H_DIM>
        <<<dim3(H_DIM / BN, (CAP + BM - 1) / BM, E_NUM), NTHREADS, SMEM_SINGLE_BYTES>>>(
            hbuf, w_down, nullptr, out);
}

// round 11
// speedup vs baseline: 3.8017x; 1.3299x over previous
#include <cuda_runtime.h>
#include <cuda_fp16.h>
#include <math.h>

#define T_TOK 2048
#define H_DIM 2048
#define E_NUM 64
#define TOPK 6
#define F_DIM 768
#define G_NUM 8
#define GSZ 8
#define KG_NUM 4
#define CAP 384
#define SCALEF 2.5f

// GEMM tile config
#define BM 128
#define BN 64
#define BK 32
#define NTHREADS 256

// smem layout (element offsets, fp16) within ONE buffer
#define SA 40                     // A row stride (80B, conflict-free for ldsm)
#define SB 72                     // B row stride
#define OFF_B     (BM * SA)               // 5120
#define BTILE     (BK * SB)               // 2304
#define BUFE_DUAL   (OFF_B + 2 * BTILE)   // 9728 elems
#define BUFE_SINGLE (OFF_B + 1 * BTILE)   // 7424 elems
#define SMEM_DUAL_BYTES   (2 * BUFE_DUAL * 2)     // 38912
#define SMEM_SINGLE_BYTES (2 * BUFE_SINGLE * 2)   // 29696

// ---------------- device scratch ----------------
__device__ int    g_cnt[E_NUM];
__device__ int    g_tok[E_NUM * CAP];
__device__ float  g_wt [E_NUM * CAP];
__device__ __half g_x16  [(size_t)T_TOK * H_DIM];          // 8 MB
__device__ __half g_hbuf16[(size_t)E_NUM * CAP * F_DIM];   // 37.7 MB
__device__ __half g_tmp16 [(size_t)T_TOK * F_DIM];         // 3.1 MB

// ---------------- helpers ----------------
__device__ __forceinline__ void ldsm4(unsigned r[4], unsigned addr) {
    asm volatile("ldmatrix.sync.aligned.m8n8.x4.shared.b16 {%0,%1,%2,%3}, [%4];\n"
        : "=r"(r[0]), "=r"(r[1]), "=r"(r[2]), "=r"(r[3]) : "r"(addr));
}
__device__ __forceinline__ void ldsm4t(unsigned r[4], unsigned addr) {
    asm volatile("ldmatrix.sync.aligned.m8n8.x4.trans.shared.b16 {%0,%1,%2,%3}, [%4];\n"
        : "=r"(r[0]), "=r"(r[1]), "=r"(r[2]), "=r"(r[3]) : "r"(addr));
}
__device__ __forceinline__ void mma_f16(float c[4], const unsigned a[4],
                                        unsigned b0, unsigned b1) {
    asm volatile(
        "mma.sync.aligned.m16n8k16.row.col.f32.f16.f16.f32 "
        "{%0,%1,%2,%3},{%4,%5,%6,%7},{%8,%9},{%0,%1,%2,%3};\n"
        : "+f"(c[0]), "+f"(c[1]), "+f"(c[2]), "+f"(c[3])
        : "r"(a[0]), "r"(a[1]), "r"(a[2]), "r"(a[3]), "r"(b0), "r"(b1));
}
// B: fp32 -> fp16 (single) vectorized store
__device__ __forceinline__ void store_b(__half* dst, int off, float4 v) {
    union { __half b[4]; uint2 u; } H;
    H.b[0] = __float2half_rn(v.x);
    H.b[1] = __float2half_rn(v.y);
    H.b[2] = __float2half_rn(v.z);
    H.b[3] = __float2half_rn(v.w);
    *(uint2*)(dst + off) = H.u;
}

// ---------------- small kernels ----------------
__global__ void zero_cnt_kernel() {
    if (threadIdx.x < E_NUM) g_cnt[threadIdx.x] = 0;
}

// x fp32 -> fp16 (4 elems / thread)
__global__ void conv_x_kernel(const float* __restrict__ x) {
    int i = blockIdx.x * blockDim.x + threadIdx.x;
    float4 v = *(const float4*)(x + (size_t)i * 4);
    union { __half b[4]; uint2 u; } H;
    H.b[0] = __float2half_rn(v.x);
    H.b[1] = __float2half_rn(v.y);
    H.b[2] = __float2half_rn(v.z);
    H.b[3] = __float2half_rn(v.w);
    *(uint2*)(g_x16 + (size_t)i * 4) = H.u;
}

__global__ void router_kernel(const float* __restrict__ x,
                              const float* __restrict__ gw,
                              const float* __restrict__ bias) {
    int t = blockIdx.x;
    int tid = threadIdx.x;
    int e = tid & 63, part = tid >> 6;
    __shared__ float ps[4][E_NUM];
    __shared__ float sc[E_NUM];
    __shared__ float scb[E_NUM];

    const float* xr = x + (size_t)t * H_DIM;
    float acc = 0.f;
    int h0 = part * (H_DIM / 4);
    #pragma unroll 4
    for (int h = 0; h < H_DIM / 4; h++)
        acc += xr[h0 + h] * gw[(size_t)(h0 + h) * E_NUM + e];
    ps[part][e] = acc;
    __syncthreads();

    if (tid < E_NUM) {
        float l = ps[0][e] + ps[1][e] + ps[2][e] + ps[3][e];
        float s = 1.f / (1.f + __expf(-l));
        sc[e] = s;
        scb[e] = s + bias[e];
    }
    __syncthreads();

    if (tid == 0) {
        float gsc[G_NUM];
        for (int g = 0; g < G_NUM; g++) {
            float m1 = -1e30f, m2 = -1e30f;
            for (int i = 0; i < GSZ; i++) {
                float v = scb[g * GSZ + i];
                if (v > m1) { m2 = m1; m1 = v; }
                else if (v > m2) { m2 = v; }
            }
            gsc[g] = m1 + m2;
        }
        bool gsel[G_NUM];
        for (int g = 0; g < G_NUM; g++) gsel[g] = false;
        for (int r = 0; r < KG_NUM; r++) {
            int bi = -1; float bv = -1e30f;
            for (int g = 0; g < G_NUM; g++)
                if (!gsel[g] && gsc[g] > bv) { bv = gsc[g]; bi = g; }
            gsel[bi] = true;
        }
        bool esel[E_NUM];
        for (int i = 0; i < E_NUM; i++) esel[i] = false;
        int ids[TOPK]; float ws[TOPK]; float wsum = 0.f;
        for (int r = 0; r < TOPK; r++) {
            int bi = -1; float bv = -1e30f;
            for (int ee = 0; ee < E_NUM; ee++) {
                if (!gsel[ee / GSZ] || esel[ee]) continue;
                float v = scb[ee];
                if (v > bv) { bv = v; bi = ee; }
            }
            esel[bi] = true; ids[r] = bi; ws[r] = sc[bi]; wsum += sc[bi];
        }
        float inv = SCALEF / wsum;
        for (int r = 0; r < TOPK; r++) {
            int ee = ids[r];
            int slot = atomicAdd(&g_cnt[ee], 1);
            if (slot < CAP) {
                g_tok[ee * CAP + slot] = t;
                g_wt [ee * CAP + slot] = ws[r] * inv;
            }
        }
    }
}

// ---------------- tensor-core GEMM (single fp16 x fp16, 2 CTA/SM) ------------
// A: fp16 global (x16 or hbuf16/tmp16). B: fp32 weights, converted in-loop.
// DUAL: C = fp16 global (silu(g)*u). SINGLE: C = fp32 (scatter-atomicAdd or plain).
template<bool EXPERT, bool DUAL, int KDIM, int NDIM>
__global__ __launch_bounds__(NTHREADS, 2)
void mma_gemm(const __half* __restrict__ Abase,
              const float* __restrict__ W0base,
              const float* __restrict__ W1base,
              void* __restrict__ Cbase) {
    constexpr bool GATHER  = EXPERT && DUAL;
    constexpr bool SCATTER = EXPERT && !DUAL;
    constexpr int  BUFE    = DUAL ? BUFE_DUAL : BUFE_SINGLE;

    const int e = EXPERT ? blockIdx.z : 0;
    const int M = EXPERT ? min(g_cnt[e], CAP) : T_TOK;
    const int m0 = blockIdx.y * BM;
    if (m0 >= M) return;
    const int n0 = blockIdx.x * BN;

    const int* toks = EXPERT ? (g_tok + e * CAP) : nullptr;
    const __half* A = GATHER ? Abase
                             : (EXPERT ? Abase + (size_t)e * CAP * KDIM : Abase);
    const float* W0 = EXPERT ? W0base + (size_t)e * KDIM * NDIM : W0base;
    const float* W1 = nullptr;
    if (DUAL) W1 = EXPERT ? W1base + (size_t)e * KDIM * NDIM : W1base;
    // per-expert output slice for the DUAL expert GEMM (writes into g_hbuf16)
    __half* Ch = (DUAL && EXPERT)
                   ? ((__half*)Cbase + (size_t)e * CAP * NDIM)
                   : (__half*)Cbase;
    float*  Cf = (float*)Cbase;

    extern __shared__ char smem_raw[];
    __half* sm = (__half*)smem_raw;

    const int tid  = threadIdx.x;
    const int lane = tid & 31;
    const int wid  = tid >> 5;
    const int wm = wid & 3;     // 4 warp rows (32 m each)
    const int wn = wid >> 2;    // 2 warp cols (32 n each)

    // ----- staging assignments -----
    // A: 128 rows x 32 halves (64B/row) = 512 x 16B chunks -> 2 per thread
    const __half* aptr[2];
    int aoffs[2];
    #pragma unroll
    for (int i = 0; i < 2; i++) {
        int idx = tid + i * NTHREADS;
        int row = idx >> 2;              // 0..127
        int c8  = (idx & 3) * 8;         // half offset within row
        aoffs[i] = row * SA + c8;
        int gr = m0 + row;
        if (GATHER) {
            int tk = (gr < M) ? toks[gr] : toks[0];
            aptr[i] = A + (size_t)tk * KDIM + c8;
        } else {
            int r = (gr < M) ? gr : (M - 1);
            aptr[i] = A + (size_t)r * KDIM + c8;
        }
    }
    // B: 32x64 fp32 = 512 float4 over 256 threads -> 2 each (per matrix)
    const float* bptr0[2];
    const float* bptr1[2];
    int boffs[2];
    #pragma unroll
    for (int i = 0; i < 2; i++) {
        int idx = tid + i * NTHREADS;
        int row = idx >> 4;              // 0..31
        int c4  = (idx & 15) * 4;
        boffs[i] = row * SB + c4;
        bptr0[i] = W0 + (size_t)row * NDIM + n0 + c4;
        if (DUAL) bptr1[i] = W1 + (size_t)row * NDIM + n0 + c4;
    }

    // ----- ldmatrix addresses (relative to buffer start) -----
    unsigned sbase = (unsigned)__cvta_generic_to_shared(smem_raw);
    const int ar  = lane & 15;
    const int ac8 = (lane >> 4) * 8;
    unsigned a_rel = ((wm * 32 + ar) * SA + ac8) * 2;
    unsigned b_rel = (OFF_B + (lane & 15) * SB + wn * 32 + ac8) * 2;

    float accg[2][4][4] = {};
    float accu[2][4][4] = {};

    // prefetch registers
    uint4  avr[2];
    float4 bvr0[2], bvr1[2];

    // prologue: load tile 0
    #pragma unroll
    for (int i = 0; i < 2; i++) avr[i] = *(const uint4*)(aptr[i]);
    #pragma unroll
    for (int i = 0; i < 2; i++) {
        bvr0[i] = *(const float4*)(bptr0[i]);
        if (DUAL) bvr1[i] = *(const float4*)(bptr1[i]);
    }

    constexpr int NIT = KDIM / BK;
    #pragma unroll 1
    for (int it = 0; it < NIT; it++) {
        const int bufo = (it & 1) ? BUFE : 0;
        __half* Ah = sm + bufo;
        __half* B0 = sm + bufo + OFF_B;
        __half* B1 = B0 + BTILE;

        // STS current prefetch
        #pragma unroll
        for (int i = 0; i < 2; i++)
            *(uint4*)(Ah + aoffs[i]) = avr[i];
        #pragma unroll
        for (int i = 0; i < 2; i++) {
            store_b(B0, boffs[i], bvr0[i]);
            if (DUAL) store_b(B1, boffs[i], bvr1[i]);
        }

        // LDG next tile
        if (it + 1 < NIT) {
            const int k = (it + 1) * BK;
            #pragma unroll
            for (int i = 0; i < 2; i++) avr[i] = *(const uint4*)(aptr[i] + k);
            #pragma unroll
            for (int i = 0; i < 2; i++) {
                bvr0[i] = *(const float4*)(bptr0[i] + (size_t)k * NDIM);
                if (DUAL) bvr1[i] = *(const float4*)(bptr1[i] + (size_t)k * NDIM);
            }
        }
        __syncthreads();

        // compute on this buffer
        const unsigned a_addr = sbase + bufo * 2 + a_rel;
        const unsigned b_addr = sbase + bufo * 2 + b_rel;
        #pragma unroll
        for (int kk = 0; kk < BK; kk += 16) {
            unsigned ah[2][4];
            #pragma unroll
            for (int mi = 0; mi < 2; mi++)
                ldsm4(ah[mi], a_addr + (mi * 16 * SA + kk) * 2);
            #pragma unroll
            for (int nj = 0; nj < 2; nj++) {
                unsigned bh[4];
                ldsm4t(bh, b_addr + (kk * SB + nj * 16) * 2);
                #pragma unroll
                for (int mi = 0; mi < 2; mi++)
                    #pragma unroll
                    for (int s = 0; s < 2; s++)
                        mma_f16(accg[mi][nj * 2 + s], ah[mi], bh[2 * s], bh[2 * s + 1]);
            }
            if (DUAL) {
                #pragma unroll
                for (int nj = 0; nj < 2; nj++) {
                    unsigned bh[4];
                    ldsm4t(bh, b_addr + (BTILE + kk * SB + nj * 16) * 2);
                    #pragma unroll
                    for (int mi = 0; mi < 2; mi++)
                        #pragma unroll
                        for (int s = 0; s < 2; s++)
                            mma_f16(accu[mi][nj * 2 + s], ah[mi], bh[2 * s], bh[2 * s + 1]);
                }
            }
        }
        __syncthreads();
    }

    // ----- epilogue -----
    const int g  = lane >> 2;
    const int t4 = lane & 3;
    #pragma unroll
    for (int mi = 0; mi < 2; mi++) {
        #pragma unroll
        for (int nc = 0; nc < 4; nc++) {
            int col = n0 + wn * 32 + nc * 8 + t4 * 2;
            #pragma unroll
            for (int h = 0; h < 2; h++) {
                int m = m0 + wm * 32 + mi * 16 + g + h * 8;
                if (m >= M) continue;
                float c0 = accg[mi][nc][h * 2];
                float c1 = accg[mi][nc][h * 2 + 1];
                if (DUAL) {
                    float u0 = accu[mi][nc][h * 2];
                    float u1 = accu[mi][nc][h * 2 + 1];
                    float v0 = c0 / (1.f + __expf(-c0)) * u0;
                    float v1 = c1 / (1.f + __expf(-c1)) * u1;
                    __half2 o = __floats2half2_rn(v0, v1);
                    *(__half2*)(Ch + (size_t)m * NDIM + col) = o;
                } else if (SCATTER) {
                    float w = g_wt[e * CAP + m];
                    float* o = Cf + (size_t)toks[m] * NDIM + col;
                    atomicAdd(o, c0 * w);
                    atomicAdd(o + 1, c1 * w);
                } else {
                    *(float2*)(Cf + (size_t)m * NDIM + col) = make_float2(c0, c1);
                }
            }
        }
    }
}

// ---------------- launch ----------------
extern "C" void kernel_launch(void* const* d_in, const int* in_sizes, int n_in,
                              void* d_out, int out_size) {
    const float* x       = (const float*)d_in[0];
    const float* gate_w  = (const float*)d_in[1];
    const float* bias    = (const float*)d_in[2];
    const float* w_gate  = (const float*)d_in[3];
    const float* w_up    = (const float*)d_in[4];
    const float* w_down  = (const float*)d_in[5];
    const float* ws_gate = (const float*)d_in[6];
    const float* ws_up   = (const float*)d_in[7];
    const float* ws_down = (const float*)d_in[8];
    float* out = (float*)d_out;

    __half* x16;  cudaGetSymbolAddress((void**)&x16,  g_x16);
    __half* hbuf; cudaGetSymbolAddress((void**)&hbuf, g_hbuf16);
    __half* tmp;  cudaGetSymbolAddress((void**)&tmp,  g_tmp16);

    cudaFuncSetAttribute(mma_gemm<false, true,  H_DIM, F_DIM>,
                         cudaFuncAttributeMaxDynamicSharedMemorySize, SMEM_DUAL_BYTES);
    cudaFuncSetAttribute(mma_gemm<false, false, F_DIM, H_DIM>,
                         cudaFuncAttributeMaxDynamicSharedMemorySize, SMEM_SINGLE_BYTES);
    cudaFuncSetAttribute(mma_gemm<true,  true,  H_DIM, F_DIM>,
                         cudaFuncAttributeMaxDynamicSharedMemorySize, SMEM_DUAL_BYTES);
    cudaFuncSetAttribute(mma_gemm<true,  false, F_DIM, H_DIM>,
                         cudaFuncAttributeMaxDynamicSharedMemorySize, SMEM_SINGLE_BYTES);

    zero_cnt_kernel<<<1, 64>>>();
    conv_x_kernel<<<(T_TOK * H_DIM / 4) / 256, 256>>>(x);
    router_kernel<<<T_TOK, 256>>>(x, gate_w, bias);

    // shared expert (plain stores initialize d_out)
    mma_gemm<false, true, H_DIM, F_DIM>
        <<<dim3(F_DIM / BN, T_TOK / BM, 1), NTHREADS, SMEM_DUAL_BYTES>>>(
            x16, ws_gate, ws_up, tmp);
    mma_gemm<false, false, F_DIM, H_DIM>
        <<<dim3(H_DIM / BN, T_TOK / BM, 1), NTHREADS, SMEM_SINGLE_BYTES>>>(
            tmp, ws_down, nullptr, out);

    // routed experts
    mma_gemm<true, true, H_DIM, F_DIM>
        <<<dim3(F_DIM / BN, (CAP + BM - 1) / BM, E_NUM), NTHREADS, SMEM_DUAL_BYTES>>>(
            x16, w_gate, w_up, hbuf);
    mma_gemm<true, false, F_DIM, H_DIM>
        <<<dim3(H_DIM / BN, (CAP + BM - 1) / BM, E_NUM), NTHREADS, SMEM_SINGLE_BYTES>>>(
            hbuf, w_down, nullptr, out);
}